// round 8
// baseline (speedup 1.0000x reference)
#include <cuda_runtime.h>
#include <cuda_fp16.h>
#include <math.h>
#include <stdint.h>

#define BATCH 4
#define LSEQ 2048
#define DMODEL 1024
#define NHEADS 8
#define DHEAD 128
#define MROWS (BATCH*LSEQ)

// ---------------- device scratch --------------------------------------------
__device__ __half g_Wt[5120*1024];                // transposed weights [n][k] fp16
__device__ __half g_Xr[MROWS*DMODEL];             // fp16 X
__device__ __half g_Q [BATCH*NHEADS*LSEQ*DHEAD];  // [b,h,l,e]
__device__ __half g_K [BATCH*NHEADS*LSEQ*DHEAD];
__device__ __half g_Vt[BATCH*NHEADS*DHEAD*LSEQ];  // [b,h,v,l]
__device__ float  g_Y [BATCH*NHEADS*LSEQ*DHEAD];
__device__ float  g_Yn[MROWS*DMODEL];
__device__ __half g_Sx[MROWS*DMODEL];             // silu(G)*Yn fp16
__device__ float g_qc[LSEQ*64];
__device__ float g_qs[LSEQ*64];
__device__ float g_kc[LSEQ*64];
__device__ float g_ks[LSEQ*64];
__device__ float g_pn[NHEADS*LSEQ];               // gamma^l
__device__ float g_pm[NHEADS*LSEQ];               // gamma^-l

// ---------------- helpers ----------------------------------------------------
__device__ __forceinline__ uint32_t smem_u32(const void* p) {
    uint32_t a;
    asm("{ .reg .u64 t; cvta.to.shared.u64 t, %1; cvt.u32.u64 %0, t; }" : "=r"(a) : "l"(p));
    return a;
}
__device__ __forceinline__ void mma16(float d[4], uint32_t a0, uint32_t a1, uint32_t a2, uint32_t a3,
                                      uint32_t b0, uint32_t b1) {
    asm volatile(
        "mma.sync.aligned.m16n8k16.row.col.f32.f16.f16.f32 "
        "{%0,%1,%2,%3}, {%4,%5,%6,%7}, {%8,%9}, {%0,%1,%2,%3};"
        : "+f"(d[0]), "+f"(d[1]), "+f"(d[2]), "+f"(d[3])
        : "r"(a0), "r"(a1), "r"(a2), "r"(a3), "r"(b0), "r"(b1));
}
#define LDSM4(r, a) \
    asm volatile("ldmatrix.sync.aligned.m8n8.x4.shared.b16 {%0,%1,%2,%3}, [%4];" \
        : "=r"((r)[0]), "=r"((r)[1]), "=r"((r)[2]), "=r"((r)[3]) : "r"(a))
#define CP16(dst, src)  asm volatile("cp.async.cg.shared.global [%0], [%1], 16;" :: "r"(dst), "l"(src) : "memory")
#define CPCOMMIT()      asm volatile("cp.async.commit_group;" ::: "memory")
#define CPWAIT0()       asm volatile("cp.async.wait_group 0;" ::: "memory")
#define CPWAIT1()       asm volatile("cp.async.wait_group 1;" ::: "memory")

// ---------------- table init -------------------------------------------------
__global__ void init_tables_kernel() {
    int idx = blockIdx.x*blockDim.x + threadIdx.x;
    if (idx < LSEQ*64) {
        int l = idx >> 6, j = idx & 63;
        float dh = (float)DHEAD;
        float base = (2.f*(float)j + 0.4f*dh) / (1.4f*dh);
        float scale = powf(base, (float)l / 512.0f);
        float inv_freq = powf(10000.0f, -(float)j / 64.0f);
        float arg = (float)l * inv_freq;
        float sv = sinf(arg), cv = cosf(arg);
        g_qc[idx] = cv * scale;
        g_qs[idx] = sv * scale;
        float iscale = 1.0f / scale;
        g_kc[idx] = cv * iscale;
        g_ks[idx] = sv * iscale;
    }
    if (idx < NHEADS*LSEQ) {
        int h = idx >> 11, k = idx & (LSEQ-1);
        float lg0 = logf(1.0f/32.0f), lg1 = logf(1.0f/512.0f);
        float lg = lg0 + (lg1 - lg0) * ((float)h / (float)(NHEADS-1));
        float gamma = 1.0f - expf(lg);
        double lng = (double)logf(gamma);
        g_pn[idx] = (float)exp((double)k * lng);
        g_pm[idx] = (float)exp(-(double)k * lng);
    }
}

// ---------------- X -> fp16 --------------------------------------------------
__global__ void roundx_kernel(const float* __restrict__ X) {
    int idx = blockIdx.x*blockDim.x + threadIdx.x;   // over /8
    float4 v0 = ((const float4*)X)[idx*2];
    float4 v1 = ((const float4*)X)[idx*2 + 1];
    __half2 h[4];
    h[0] = __floats2half2_rn(v0.x, v0.y);
    h[1] = __floats2half2_rn(v0.z, v0.w);
    h[2] = __floats2half2_rn(v1.x, v1.y);
    h[3] = __floats2half2_rn(v1.z, v1.w);
    *(uint4*)(g_Xr + (size_t)idx*8) = *(uint4*)h;
}

// ---------------- weight transpose -> fp16 ----------------------------------
__global__ void wtrans_kernel(const float* __restrict__ WQ, const float* __restrict__ WK,
                              const float* __restrict__ WV, const float* __restrict__ WG,
                              const float* __restrict__ WO) {
    __shared__ float t[32][33];
    int kT = blockIdx.x << 5, nT = blockIdx.y << 5;
    int tx = threadIdx.x, ty = threadIdx.y;   // 32 x 8
    #pragma unroll
    for (int r = 0; r < 4; r++) {
        int n = nT + tx, k = kT + ty + 8*r;
        float v;
        if (n < 3072) {
            int sel = n >> 10, h = (n >> 7) & 7, e = n & 127;
            const float* W = (sel == 0) ? WQ : (sel == 1) ? WK : WV;
            v = W[(size_t)h*131072 + (size_t)k*128 + e];
        } else if (n < 4096) {
            v = WG[(size_t)k*1024 + (n - 3072)];
        } else {
            v = WO[(size_t)k*1024 + (n - 4096)];
        }
        t[ty + 8*r][tx] = v;
    }
    __syncthreads();
    #pragma unroll
    for (int r = 0; r < 4; r++) {
        int n = nT + ty + 8*r, k = kT + tx;
        g_Wt[(size_t)n*1024 + k] = __float2half(t[tx][ty + 8*r]);
    }
}

// ---------------- unified fp16 mma GEMM (ldmatrix) ---------------------------
// 256 thr, 8 warps (4x2), warp tile 32x64. k-chunks of 64, double buffered.
// smem halves: A[2][128][72], B[2][128][72]
#define MM_SMEM (36864*2)
__global__ __launch_bounds__(256) void mm_kernel(float* __restrict__ Cout, int mode, int wRowOff) {
    extern __shared__ __half smh[];
    const int tid = threadIdx.x;
    const int wid = tid >> 5, lane = tid & 31;
    const int q = lane >> 2, tq = lane & 3;
    const int wm = wid & 3, wn = wid >> 1 >> 1;   // wn = wid >> 2
    const int rb = blockIdx.y << 7, cb = blockIdx.x << 7;

    const __half* Ap = ((mode == 2) ? g_Sx : g_Xr) + (size_t)rb * 1024;
    const __half* Bp = g_Wt + (size_t)(wRowOff + cb) * 1024;

    uint32_t smb = smem_u32(smh);
    uint32_t asb[2] = { smb, smb + 9216u*2u };
    uint32_t bsb[2] = { smb + 18432u*2u, smb + 27648u*2u };

    // ldmatrix per-thread offsets (bytes)
    const uint32_t aoff = (uint32_t)(((wm*32 + (lane & 15))*72 + (lane >> 4)*8) * 2);
    const uint32_t boff = (uint32_t)(((wn*64 + ((lane >> 4) << 3) + (lane & 7))*72 + ((lane >> 3) & 1)*8) * 2);

    float acc[2][8][4];
    #pragma unroll
    for (int mi = 0; mi < 2; mi++)
        #pragma unroll
        for (int ni = 0; ni < 8; ni++)
            #pragma unroll
            for (int c = 0; c < 4; c++) acc[mi][ni][c] = 0.0f;

    // prologue: chunk 0 (per buf: 128 rows x 64 halves = 16KB => 1024 cp16; 4/thread)
    #pragma unroll
    for (int i = 0; i < 4; i++) {
        int ch = tid + (i << 8);
        int r = ch >> 3, c8 = (ch & 7) << 3;
        CP16(asb[0] + (uint32_t)(r*72 + c8)*2u, Ap + (size_t)r*1024 + c8);
        CP16(bsb[0] + (uint32_t)(r*72 + c8)*2u, Bp + (size_t)r*1024 + c8);
    }
    CPCOMMIT();

    #pragma unroll 1
    for (int k = 0; k < 16; k++) {
        int buf = k & 1;
        if (k + 1 < 16) {
            int kt = (k + 1) * 64, nb_ = buf ^ 1;
            #pragma unroll
            for (int i = 0; i < 4; i++) {
                int ch = tid + (i << 8);
                int r = ch >> 3, c8 = (ch & 7) << 3;
                CP16(asb[nb_] + (uint32_t)(r*72 + c8)*2u, Ap + (size_t)r*1024 + kt + c8);
                CP16(bsb[nb_] + (uint32_t)(r*72 + c8)*2u, Bp + (size_t)r*1024 + kt + c8);
            }
            CPCOMMIT();
            CPWAIT1();
        } else {
            CPWAIT0();
        }
        __syncthreads();
        uint32_t ab = asb[buf] + aoff;
        uint32_t bb = bsb[buf] + boff;
        #pragma unroll
        for (int ks = 0; ks < 4; ks++) {
            uint32_t af0[4], af1[4];
            LDSM4(af0, ab + ks*32);
            LDSM4(af1, ab + ks*32 + 2304);     // +16 rows * 72 halves * 2B
            #pragma unroll
            for (int nj = 0; nj < 4; nj++) {
                uint32_t bf[4];
                LDSM4(bf, bb + ks*32 + nj*2304);
                mma16(acc[0][2*nj],   af0[0], af0[1], af0[2], af0[3], bf[0], bf[1]);
                mma16(acc[0][2*nj+1], af0[0], af0[1], af0[2], af0[3], bf[2], bf[3]);
                mma16(acc[1][2*nj],   af1[0], af1[1], af1[2], af1[3], bf[0], bf[1]);
                mma16(acc[1][2*nj+1], af1[0], af1[1], af1[2], af1[3], bf[2], bf[3]);
            }
        }
        __syncthreads();
    }

    // ---------------- epilogue ----------------
    int sel = 0, hh = 0;
    if (mode == 0) { sel = blockIdx.x >> 3; hh = blockIdx.x & 7; }

    #pragma unroll
    for (int mi = 0; mi < 2; mi++) {
        #pragma unroll
        for (int half_ = 0; half_ < 2; half_++) {
            int row = rb + wm*32 + mi*16 + q + half_*8;
            int bb2 = row >> 11, l = row & (LSEQ - 1);
            #pragma unroll
            for (int ni = 0; ni < 8; ni++) {
                int colb = wn*64 + ni*8 + 2*tq;
                float x1 = acc[mi][ni][half_*2 + 0];
                float x2 = acc[mi][ni][half_*2 + 1];
                if (mode == 0) {
                    size_t hbase = (size_t)(bb2*NHEADS + hh);
                    if (sel == 2) {
                        __half* vt = g_Vt + hbase * (size_t)(DHEAD*LSEQ);
                        vt[(size_t)colb * LSEQ + l]       = __float2half(x1);
                        vt[(size_t)(colb + 1) * LSEQ + l] = __float2half(x2);
                    } else {
                        const float* ct = (sel == 0) ? g_qc : g_kc;
                        const float* st = (sel == 0) ? g_qs : g_ks;
                        int jj = colb >> 1;
                        float cv = ct[l*64 + jj], sv = st[l*64 + jj];
                        __half2 o = __floats2half2_rn(x1*cv - x2*sv, x2*cv + x1*sv);
                        __half* dst = ((sel == 0) ? g_Q : g_K) + (hbase*LSEQ + l)*DHEAD + colb;
                        *(__half2*)dst = o;
                    }
                } else if (mode == 1) {
                    size_t off = (size_t)row*1024 + cb + colb;
                    float2 yn = *(const float2*)(g_Yn + off);
                    __half2 o = __floats2half2_rn((x1 / (1.0f + expf(-x1))) * yn.x,
                                                  (x2 / (1.0f + expf(-x2))) * yn.y);
                    *(__half2*)(g_Sx + off) = o;
                } else {
                    size_t off = (size_t)row*1024 + cb + colb;
                    *(float2*)(Cout + off) = make_float2(x1, x2);
                }
            }
        }
    }
}

// ---------------- attention: fp16, ldmatrix, pipelined -----------------------
// smem halves: Qs[128][136] | Ks[2][64][136] | Vs[2][128][72] | Ss[128][72]
#define QS_O  0
#define KS0_O 17408
#define KS1_O 26112
#define VS0_O 34816
#define VS1_O 44032
#define SS_O  53248
#define ATT_SMEM (62464*2)
__global__ __launch_bounds__(256) void attn_kernel() {
    extern __shared__ __half smh[];
    __half* Ss = smh + SS_O;
    uint32_t smb = smem_u32(smh);
    uint32_t qsb = smb + QS_O*2u;
    uint32_t ksb[2] = { smb + KS0_O*2u, smb + KS1_O*2u };
    uint32_t vsb[2] = { smb + VS0_O*2u, smb + VS1_O*2u };
    uint32_t ssb = smb + SS_O*2u;

    const int tid = threadIdx.x;
    const int wid = tid >> 5, lane = tid & 31;
    const int q = lane >> 2, tq = lane & 3;
    const int wm = wid & 3, wn = wid >> 2;

    int nt = (int)(gridDim.x - 1) - (int)blockIdx.x;   // big tiles first
    int h = blockIdx.y, b = blockIdx.z;
    int nb = nt << 7;

    size_t hb = (size_t)(b*NHEADS + h);
    const __half* Qg = g_Q + hb * (size_t)(LSEQ*DHEAD);
    const __half* Kg = g_K + hb * (size_t)(LSEQ*DHEAD);
    const __half* Vg = g_Vt + hb * (size_t)(DHEAD*LSEQ);
    float* Yg = g_Y + hb * (size_t)(LSEQ*DHEAD);
    const float* pm = g_pm + h*LSEQ;

    float pn[2][2];
    #pragma unroll
    for (int mi = 0; mi < 2; mi++)
        #pragma unroll
        for (int hf = 0; hf < 2; hf++)
            pn[mi][hf] = g_pn[h*LSEQ + nb + wm*32 + mi*16 + q + hf*8];

    // ldmatrix per-thread offsets (bytes)
    const uint32_t qoff = (uint32_t)(((wm*32 + (lane & 15))*136 + (lane >> 4)*8) * 2);
    const uint32_t koff = (uint32_t)(((wn*32 + ((lane >> 4) << 3) + (lane & 7))*136 + ((lane >> 3) & 1)*8) * 2);
    const uint32_t soff = (uint32_t)(((wm*32 + (lane & 15))*72 + (lane >> 4)*8) * 2);
    const uint32_t voff = (uint32_t)(((wn*64 + ((lane >> 4) << 3) + (lane & 7))*72 + ((lane >> 3) & 1)*8) * 2);

    // prologue: Q (32KB: 8 cp16/thr) + K[0] (16KB: 4/thr) + V[0] (16KB: 4/thr)
    {
        int r = tid >> 1, part = (tid & 1) * 64;
        const __half* src = Qg + (size_t)(nb + r)*DHEAD + part;
        #pragma unroll
        for (int i = 0; i < 8; i++)
            CP16(qsb + (uint32_t)(r*136 + part + i*8)*2u, src + i*8);
        int kr = tid >> 2, kc = (tid & 3) * 32;
        const __half* ksrc = Kg + (size_t)kr*DHEAD + kc;
        #pragma unroll
        for (int i = 0; i < 4; i++)
            CP16(ksb[0] + (uint32_t)(kr*136 + kc + i*8)*2u, ksrc + i*8);
        int vr = tid >> 1, vc = (tid & 1) * 32;
        const __half* vsrc = Vg + (size_t)vr*LSEQ + vc;
        #pragma unroll
        for (int i = 0; i < 4; i++)
            CP16(vsb[0] + (uint32_t)(vr*72 + vc + i*8)*2u, vsrc + i*8);
        CPCOMMIT();
    }

    float yacc[2][8][4];
    #pragma unroll
    for (int mi = 0; mi < 2; mi++)
        #pragma unroll
        for (int ni = 0; ni < 8; ni++)
            #pragma unroll
            for (int c = 0; c < 4; c++) yacc[mi][ni][c] = 0.0f;

    int nMt = 2*nt + 2;
    #pragma unroll 1
    for (int mt = 0; mt < nMt; mt++) {
        int mb_ = mt << 6;
        int buf = mt & 1;
        CPWAIT0();              // K[mt], V[mt] resident
        __syncthreads();        // all warps past Y(mt-1): other buffers free

        // issue K[mt+1] + V[mt+1] into the other buffers (hidden under compute)
        if (mt + 1 < nMt) {
            int kr = tid >> 2, kc = (tid & 3) * 32;
            const __half* ksrc = Kg + (size_t)(mb_ + 64 + kr)*DHEAD + kc;
            #pragma unroll
            for (int i = 0; i < 4; i++)
                CP16(ksb[buf^1] + (uint32_t)(kr*136 + kc + i*8)*2u, ksrc + i*8);
            int vr = tid >> 1, vc = (tid & 1) * 32;
            const __half* vsrc = Vg + (size_t)vr*LSEQ + mb_ + 64 + vc;
            #pragma unroll
            for (int i = 0; i < 4; i++)
                CP16(vsb[buf^1] + (uint32_t)(vr*72 + vc + i*8)*2u, vsrc + i*8);
            CPCOMMIT();
        }

        // S = Q K^T : warp tile 32 rows x 32 cols, k-depth 128 (8 k16 steps)
        float sacc[2][4][4];
        #pragma unroll
        for (int mi = 0; mi < 2; mi++)
            #pragma unroll
            for (int ni = 0; ni < 4; ni++)
                #pragma unroll
                for (int c = 0; c < 4; c++) sacc[mi][ni][c] = 0.0f;
        {
            uint32_t qa = qsb + qoff;
            uint32_t ka = ksb[buf] + koff;
            #pragma unroll
            for (int ks = 0; ks < 8; ks++) {
                uint32_t af0[4], af1[4];
                LDSM4(af0, qa + ks*32);
                LDSM4(af1, qa + ks*32 + 4352);    // +16 rows * 136 halves * 2B
                #pragma unroll
                for (int nj = 0; nj < 2; nj++) {
                    uint32_t bf[4];
                    LDSM4(bf, ka + ks*32 + nj*4352);
                    mma16(sacc[0][2*nj],   af0[0], af0[1], af0[2], af0[3], bf[0], bf[1]);
                    mma16(sacc[0][2*nj+1], af0[0], af0[1], af0[2], af0[3], bf[2], bf[3]);
                    mma16(sacc[1][2*nj],   af1[0], af1[1], af1[2], af1[3], bf[0], bf[1]);
                    mma16(sacc[1][2*nj+1], af1[0], af1[1], af1[2], af1[3], bf[2], bf[3]);
                }
            }
        }

        // decay + store own 32x32 block of Ss (fp16)
        #pragma unroll
        for (int mi = 0; mi < 2; mi++) {
            #pragma unroll
            for (int hf = 0; hf < 2; hf++) {
                int r = wm*32 + mi*16 + q + hf*8;
                int n_ = nb + r;
                float pnv = pn[mi][hf];
                #pragma unroll
                for (int ni = 0; ni < 4; ni++) {
                    int m = wn*32 + ni*8 + 2*tq;
                    int mg = mb_ + m;
                    float2 ip = *(const float2*)(pm + mg);
                    float v0 = (n_ >= mg) ? sacc[mi][ni][hf*2+0] * (pnv*ip.x) : 0.0f;
                    float v1 = (n_ >  mg) ? sacc[mi][ni][hf*2+1] * (pnv*ip.y) : 0.0f;
                    *(__half2*)(Ss + r*72 + m) = __floats2half2_rn(v0, v1);
                }
            }
        }
        __syncthreads();   // S visible cross-warp; V[mt] already resident

        // Y += S V^T : warp tile 32 rows x 64 cols, k-depth 64 (4 k16 steps)
        {
            uint32_t sa = ssb + soff;
            uint32_t va = vsb[buf] + voff;
            #pragma unroll
            for (int ks = 0; ks < 4; ks++) {
                uint32_t af0[4], af1[4];
                LDSM4(af0, sa + ks*32);
                LDSM4(af1, sa + ks*32 + 2304);    // +16 rows * 72 halves * 2B
                #pragma unroll
                for (int nj = 0; nj < 4; nj++) {
                    uint32_t bf[4];
                    LDSM4(bf, va + ks*32 + nj*2304);
                    mma16(yacc[0][2*nj],   af0[0], af0[1], af0[2], af0[3], bf[0], bf[1]);
                    mma16(yacc[0][2*nj+1], af0[0], af0[1], af0[2], af0[3], bf[2], bf[3]);
                    mma16(yacc[1][2*nj],   af1[0], af1[1], af1[2], af1[3], bf[0], bf[1]);
                    mma16(yacc[1][2*nj+1], af1[0], af1[1], af1[2], af1[3], bf[2], bf[3]);
                }
            }
        }
    }

    // write Y (f32)
    #pragma unroll
    for (int mi = 0; mi < 2; mi++) {
        #pragma unroll
        for (int hf = 0; hf < 2; hf++) {
            int row = wm*32 + mi*16 + q + hf*8;
            #pragma unroll
            for (int ni = 0; ni < 8; ni++) {
                int v = wn*64 + ni*8 + 2*tq;
                *(float2*)(Yg + (size_t)(nb + row)*DHEAD + v) =
                    make_float2(yacc[mi][ni][hf*2+0], yacc[mi][ni][hf*2+1]);
            }
        }
    }
}

// ---------------- group norm over head dim (128), transpose to [b,l,d] ------
__global__ __launch_bounds__(256) void groupnorm_kernel(
    const float* __restrict__ gw, const float* __restrict__ gb)
{
    int gtid = blockIdx.x*blockDim.x + threadIdx.x;
    int warp = gtid >> 5;
    int lane = gtid & 31;
    if (warp >= BATCH*NHEADS*LSEQ) return;
    const float* y = g_Y + (size_t)warp * DHEAD;
    float4 v = ((const float4*)y)[lane];
    float s  = v.x + v.y + v.z + v.w;
    float ss = v.x*v.x + v.y*v.y + v.z*v.z + v.w*v.w;
    #pragma unroll
    for (int o = 16; o > 0; o >>= 1) {
        s  += __shfl_xor_sync(0xffffffffu, s,  o);
        ss += __shfl_xor_sync(0xffffffffu, ss, o);
    }
    float mean = s * (1.0f/DHEAD);
    float var  = ss * (1.0f/DHEAD) - mean*mean;
    float rstd = rsqrtf(var + 1e-5f);
    int l  = warp & (LSEQ - 1);
    int h  = (warp >> 11) & (NHEADS - 1);
    int bb = warp >> 14;
    int dcol = h*DHEAD + (lane << 2);
    float4 w4 = *(const float4*)(gw + dcol);
    float4 b4 = *(const float4*)(gb + dcol);
    float4 o;
    o.x = (v.x - mean)*rstd*w4.x + b4.x;
    o.y = (v.y - mean)*rstd*w4.y + b4.y;
    o.z = (v.z - mean)*rstd*w4.z + b4.z;
    o.w = (v.w - mean)*rstd*w4.w + b4.w;
    *(float4*)(g_Yn + (size_t)(bb*LSEQ + l)*DMODEL + dcol) = o;
}

// ---------------- launch ----------------------------------------------------
extern "C" void kernel_launch(void* const* d_in, const int* in_sizes, int n_in,
                              void* d_out, int out_size) {
    const float* X  = (const float*)d_in[0];
    const float* WQ = (const float*)d_in[1];
    const float* WK = (const float*)d_in[2];
    const float* WV = (const float*)d_in[3];
    const float* WG = (const float*)d_in[4];
    const float* WO = (const float*)d_in[5];
    const float* gw = (const float*)d_in[6];
    const float* gb = (const float*)d_in[7];
    float* out = (float*)d_out;

    cudaFuncSetAttribute(mm_kernel, cudaFuncAttributeMaxDynamicSharedMemorySize, MM_SMEM);
    cudaFuncSetAttribute(attn_kernel, cudaFuncAttributeMaxDynamicSharedMemorySize, ATT_SMEM);

    init_tables_kernel<<<512, 256>>>();
    roundx_kernel<<<(MROWS*DMODEL/8)/256, 256>>>(X);
    wtrans_kernel<<<dim3(32, 160), dim3(32, 8)>>>(WQ, WK, WV, WG, WO);

    // QKV projection + rotary + V transpose
    mm_kernel<<<dim3(24, 64), 256, MM_SMEM>>>(nullptr, 0, 0);

    // retention attention
    attn_kernel<<<dim3(16, NHEADS, BATCH), 256, ATT_SMEM>>>();

    // group norm + transpose
    groupnorm_kernel<<<(BATCH*NHEADS*LSEQ*32)/256, 256>>>(gw, gb);

    // gate GEMM + silu*Yn
    mm_kernel<<<dim3(8, 64), 256, MM_SMEM>>>(nullptr, 1, 3072);

    // output GEMM
    mm_kernel<<<dim3(8, 64), 256, MM_SMEM>>>(out, 2, 4096);
}

// round 9
// speedup vs baseline: 1.2898x; 1.2898x over previous
#include <cuda_runtime.h>
#include <cuda_fp16.h>
#include <math.h>
#include <stdint.h>

#define BATCH 4
#define LSEQ 2048
#define DMODEL 1024
#define NHEADS 8
#define DHEAD 128
#define MROWS (BATCH*LSEQ)

// ---------------- device scratch --------------------------------------------
__device__ __half g_Wt[5120*1024];                // transposed weights [n][k] fp16
__device__ __half g_Xr[MROWS*DMODEL];             // fp16 X
__device__ __half g_Q [BATCH*NHEADS*LSEQ*DHEAD];  // [b,h,l,e]
__device__ __half g_K [BATCH*NHEADS*LSEQ*DHEAD];
__device__ __half g_Vt[BATCH*NHEADS*DHEAD*LSEQ];  // [b,h,v,l]
__device__ float  g_Y [BATCH*NHEADS*LSEQ*DHEAD];
__device__ float  g_Yn[MROWS*DMODEL];
__device__ __half g_Sx[MROWS*DMODEL];             // silu(G)*Yn fp16
__device__ float g_qc[LSEQ*64];
__device__ float g_qs[LSEQ*64];
__device__ float g_kc[LSEQ*64];
__device__ float g_ks[LSEQ*64];
__device__ float g_pn[NHEADS*LSEQ];               // gamma^l
__device__ float g_pm[NHEADS*LSEQ];               // gamma^-l

// ---------------- helpers ----------------------------------------------------
__device__ __forceinline__ uint32_t smem_u32(const void* p) {
    uint32_t a;
    asm("{ .reg .u64 t; cvta.to.shared.u64 t, %1; cvt.u32.u64 %0, t; }" : "=r"(a) : "l"(p));
    return a;
}
__device__ __forceinline__ void mma16(float d[4], uint32_t a0, uint32_t a1, uint32_t a2, uint32_t a3,
                                      uint32_t b0, uint32_t b1) {
    asm volatile(
        "mma.sync.aligned.m16n8k16.row.col.f32.f16.f16.f32 "
        "{%0,%1,%2,%3}, {%4,%5,%6,%7}, {%8,%9}, {%0,%1,%2,%3};"
        : "+f"(d[0]), "+f"(d[1]), "+f"(d[2]), "+f"(d[3])
        : "r"(a0), "r"(a1), "r"(a2), "r"(a3), "r"(b0), "r"(b1));
}
#define LDU(p) (*(const uint32_t*)(p))
#define CP16(dst, src)  asm volatile("cp.async.cg.shared.global [%0], [%1], 16;" :: "r"(dst), "l"(src) : "memory")
#define CPCOMMIT()      asm volatile("cp.async.commit_group;" ::: "memory")
#define CPWAIT0()       asm volatile("cp.async.wait_group 0;" ::: "memory")
#define CPWAIT1()       asm volatile("cp.async.wait_group 1;" ::: "memory")

// ---------------- table init -------------------------------------------------
__global__ void init_tables_kernel() {
    int idx = blockIdx.x*blockDim.x + threadIdx.x;
    if (idx < LSEQ*64) {
        int l = idx >> 6, j = idx & 63;
        float dh = (float)DHEAD;
        float base = (2.f*(float)j + 0.4f*dh) / (1.4f*dh);
        float scale = powf(base, (float)l / 512.0f);
        float inv_freq = powf(10000.0f, -(float)j / 64.0f);
        float arg = (float)l * inv_freq;
        float sv = sinf(arg), cv = cosf(arg);
        g_qc[idx] = cv * scale;
        g_qs[idx] = sv * scale;
        float iscale = 1.0f / scale;
        g_kc[idx] = cv * iscale;
        g_ks[idx] = sv * iscale;
    }
    if (idx < NHEADS*LSEQ) {
        int h = idx >> 11, k = idx & (LSEQ-1);
        float lg0 = logf(1.0f/32.0f), lg1 = logf(1.0f/512.0f);
        float lg = lg0 + (lg1 - lg0) * ((float)h / (float)(NHEADS-1));
        float gamma = 1.0f - expf(lg);
        double lng = (double)logf(gamma);
        g_pn[idx] = (float)exp((double)k * lng);
        g_pm[idx] = (float)exp(-(double)k * lng);
    }
}

// ---------------- X -> fp16 --------------------------------------------------
__global__ void roundx_kernel(const float* __restrict__ X) {
    int idx = blockIdx.x*blockDim.x + threadIdx.x;   // over /8
    float4 v0 = ((const float4*)X)[idx*2];
    float4 v1 = ((const float4*)X)[idx*2 + 1];
    __half2 h[4];
    h[0] = __floats2half2_rn(v0.x, v0.y);
    h[1] = __floats2half2_rn(v0.z, v0.w);
    h[2] = __floats2half2_rn(v1.x, v1.y);
    h[3] = __floats2half2_rn(v1.z, v1.w);
    *(uint4*)(g_Xr + (size_t)idx*8) = *(uint4*)h;
}

// ---------------- weight transpose -> fp16 ----------------------------------
__global__ void wtrans_kernel(const float* __restrict__ WQ, const float* __restrict__ WK,
                              const float* __restrict__ WV, const float* __restrict__ WG,
                              const float* __restrict__ WO) {
    __shared__ float t[32][33];
    int kT = blockIdx.x << 5, nT = blockIdx.y << 5;
    int tx = threadIdx.x, ty = threadIdx.y;   // 32 x 8
    #pragma unroll
    for (int r = 0; r < 4; r++) {
        int n = nT + tx, k = kT + ty + 8*r;
        float v;
        if (n < 3072) {
            int sel = n >> 10, h = (n >> 7) & 7, e = n & 127;
            const float* W = (sel == 0) ? WQ : (sel == 1) ? WK : WV;
            v = W[(size_t)h*131072 + (size_t)k*128 + e];
        } else if (n < 4096) {
            v = WG[(size_t)k*1024 + (n - 3072)];
        } else {
            v = WO[(size_t)k*1024 + (n - 4096)];
        }
        t[ty + 8*r][tx] = v;
    }
    __syncthreads();
    #pragma unroll
    for (int r = 0; r < 4; r++) {
        int n = nT + ty + 8*r, k = kT + tx;
        g_Wt[(size_t)n*1024 + k] = __float2half(t[tx][ty + 8*r]);
    }
}

// ---------------- unified fp16 mma GEMM (R7 known-good) ----------------------
// 256 thr, 8 warps (4x2), warp tile 32x64. k-chunks of 64, double buffered.
// smem halves: A[2][128][72], B[2][128][72]
#define MM_SMEM (36864*2)
__global__ __launch_bounds__(256) void mm_kernel(float* __restrict__ Cout, int mode, int wRowOff) {
    extern __shared__ __half smh[];
    const int tid = threadIdx.x;
    const int wid = tid >> 5, lane = tid & 31;
    const int q = lane >> 2, tq = lane & 3;
    const int wm = wid & 3, wn = wid >> 2;
    const int rb = blockIdx.y << 7, cb = blockIdx.x << 7;

    const __half* Ap = ((mode == 2) ? g_Sx : g_Xr) + (size_t)rb * 1024;
    const __half* Bp = g_Wt + (size_t)(wRowOff + cb) * 1024;

    __half* Asm[2] = { smh, smh + 9216 };
    __half* Bsm[2] = { smh + 18432, smh + 27648 };
    uint32_t smb = smem_u32(smh);
    uint32_t asb[2] = { smb, smb + 9216u*2u };
    uint32_t bsb[2] = { smb + 18432u*2u, smb + 27648u*2u };

    float acc[2][8][4];
    #pragma unroll
    for (int mi = 0; mi < 2; mi++)
        #pragma unroll
        for (int ni = 0; ni < 8; ni++)
            #pragma unroll
            for (int c = 0; c < 4; c++) acc[mi][ni][c] = 0.0f;

    // prologue: chunk 0
    #pragma unroll
    for (int i = 0; i < 4; i++) {
        int ch = tid + (i << 8);
        int r = ch >> 3, c8 = (ch & 7) << 3;
        CP16(asb[0] + (uint32_t)(r*72 + c8)*2u, Ap + (size_t)r*1024 + c8);
        CP16(bsb[0] + (uint32_t)(r*72 + c8)*2u, Bp + (size_t)r*1024 + c8);
    }
    CPCOMMIT();

    #pragma unroll 1
    for (int k = 0; k < 16; k++) {
        int buf = k & 1;
        if (k + 1 < 16) {
            int kt = (k + 1) * 64, nb_ = buf ^ 1;
            #pragma unroll
            for (int i = 0; i < 4; i++) {
                int ch = tid + (i << 8);
                int r = ch >> 3, c8 = (ch & 7) << 3;
                CP16(asb[nb_] + (uint32_t)(r*72 + c8)*2u, Ap + (size_t)r*1024 + kt + c8);
                CP16(bsb[nb_] + (uint32_t)(r*72 + c8)*2u, Bp + (size_t)r*1024 + kt + c8);
            }
            CPCOMMIT();
            CPWAIT1();
        } else {
            CPWAIT0();
        }
        __syncthreads();
        const __half* A_ = Asm[buf];
        const __half* B_ = Bsm[buf];
        #pragma unroll
        for (int ks = 0; ks < 4; ks++) {
            int c = ks*16 + 2*tq;
            uint32_t af[2][4];
            #pragma unroll
            for (int mi = 0; mi < 2; mi++) {
                int r = wm*32 + mi*16 + q;
                af[mi][0] = LDU(A_ + r*72 + c);
                af[mi][1] = LDU(A_ + (r+8)*72 + c);
                af[mi][2] = LDU(A_ + r*72 + c + 8);
                af[mi][3] = LDU(A_ + (r+8)*72 + c + 8);
            }
            #pragma unroll
            for (int ni = 0; ni < 8; ni++) {
                int n = wn*64 + ni*8 + q;
                uint32_t b0 = LDU(B_ + n*72 + c);
                uint32_t b1 = LDU(B_ + n*72 + c + 8);
                mma16(acc[0][ni], af[0][0], af[0][1], af[0][2], af[0][3], b0, b1);
                mma16(acc[1][ni], af[1][0], af[1][1], af[1][2], af[1][3], b0, b1);
            }
        }
        __syncthreads();
    }

    // ---------------- epilogue ----------------
    int sel = 0, hh = 0;
    if (mode == 0) { sel = blockIdx.x >> 3; hh = blockIdx.x & 7; }

    #pragma unroll
    for (int mi = 0; mi < 2; mi++) {
        #pragma unroll
        for (int half_ = 0; half_ < 2; half_++) {
            int row = rb + wm*32 + mi*16 + q + half_*8;
            int bb = row >> 11, l = row & (LSEQ - 1);
            #pragma unroll
            for (int ni = 0; ni < 8; ni++) {
                int colb = wn*64 + ni*8 + 2*tq;
                float x1 = acc[mi][ni][half_*2 + 0];
                float x2 = acc[mi][ni][half_*2 + 1];
                if (mode == 0) {
                    size_t hbase = (size_t)(bb*NHEADS + hh);
                    if (sel == 2) {
                        __half* vt = g_Vt + hbase * (size_t)(DHEAD*LSEQ);
                        vt[(size_t)colb * LSEQ + l]       = __float2half(x1);
                        vt[(size_t)(colb + 1) * LSEQ + l] = __float2half(x2);
                    } else {
                        const float* ct = (sel == 0) ? g_qc : g_kc;
                        const float* st = (sel == 0) ? g_qs : g_ks;
                        int jj = colb >> 1;
                        float cv = ct[l*64 + jj], sv = st[l*64 + jj];
                        __half2 o = __floats2half2_rn(x1*cv - x2*sv, x2*cv + x1*sv);
                        __half* dst = ((sel == 0) ? g_Q : g_K) + (hbase*LSEQ + l)*DHEAD + colb;
                        *(__half2*)dst = o;
                    }
                } else if (mode == 1) {
                    size_t off = (size_t)row*1024 + cb + colb;
                    float2 yn = *(const float2*)(g_Yn + off);
                    __half2 o = __floats2half2_rn((x1 / (1.0f + expf(-x1))) * yn.x,
                                                  (x2 / (1.0f + expf(-x2))) * yn.y);
                    *(__half2*)(g_Sx + off) = o;
                } else {
                    size_t off = (size_t)row*1024 + cb + colb;
                    *(float2*)(Cout + off) = make_float2(x1, x2);
                }
            }
        }
    }
}

// ---------------- attention: fp16, 64-row Q tiles, 2 CTA/SM ------------------
// 8 warps: S warp-tile 32x16 (wm in 0..1, wn in 0..3), Y warp-tile 32x32.
// smem halves: Qs[64][136] | Ks[2][64][136] | Vs[2][128][72] | Ss[64][72]
#define QS_O  0
#define KS0_O 8704
#define KS1_O 17408
#define VS0_O 26112
#define VS1_O 35328
#define SS_O  44544
#define ATT_SMEM (49152*2)
__global__ __launch_bounds__(256) void attn_kernel() {
    extern __shared__ __half smh[];
    __half* Qs = smh + QS_O;
    __half* Ks[2] = { smh + KS0_O, smh + KS1_O };
    __half* Vs[2] = { smh + VS0_O, smh + VS1_O };
    __half* Ss = smh + SS_O;
    uint32_t smb = smem_u32(smh);
    uint32_t qsb = smb + QS_O*2u;
    uint32_t ksb[2] = { smb + KS0_O*2u, smb + KS1_O*2u };
    uint32_t vsb[2] = { smb + VS0_O*2u, smb + VS1_O*2u };

    const int tid = threadIdx.x;
    const int wid = tid >> 5, lane = tid & 31;
    const int q = lane >> 2, tq = lane & 3;
    const int wm = wid & 1, wn = wid >> 1;

    int nt = (int)(gridDim.x - 1) - (int)blockIdx.x;   // big tiles first
    int h = blockIdx.y, b = blockIdx.z;
    int nb = nt << 6;

    size_t hb = (size_t)(b*NHEADS + h);
    const __half* Qg = g_Q + hb * (size_t)(LSEQ*DHEAD);
    const __half* Kg = g_K + hb * (size_t)(LSEQ*DHEAD);
    const __half* Vg = g_Vt + hb * (size_t)(DHEAD*LSEQ);
    float* Yg = g_Y + hb * (size_t)(LSEQ*DHEAD);
    const float* pm = g_pm + h*LSEQ;

    float pn[2][2];
    #pragma unroll
    for (int mi = 0; mi < 2; mi++)
        #pragma unroll
        for (int hf = 0; hf < 2; hf++)
            pn[mi][hf] = g_pn[h*LSEQ + nb + wm*32 + mi*16 + q + hf*8];

    // prologue: Q (64x128 = 16KB: 4 cp16/thr) + K[0] (4/thr) + V[0] (4/thr)
    {
        int r = tid >> 2, c = (tid & 3) * 32;
        const __half* src = Qg + (size_t)(nb + r)*DHEAD + c;
        const __half* ksrc = Kg + (size_t)r*DHEAD + c;
        #pragma unroll
        for (int i = 0; i < 4; i++) {
            CP16(qsb + (uint32_t)(r*136 + c + i*8)*2u, src + i*8);
            CP16(ksb[0] + (uint32_t)(r*136 + c + i*8)*2u, ksrc + i*8);
        }
        int vr = tid >> 1, vc = (tid & 1) * 32;
        const __half* vsrc = Vg + (size_t)vr*LSEQ + vc;
        #pragma unroll
        for (int i = 0; i < 4; i++)
            CP16(vsb[0] + (uint32_t)(vr*72 + vc + i*8)*2u, vsrc + i*8);
        CPCOMMIT();
    }

    float yacc[2][4][4];
    #pragma unroll
    for (int mi = 0; mi < 2; mi++)
        #pragma unroll
        for (int ni = 0; ni < 4; ni++)
            #pragma unroll
            for (int c = 0; c < 4; c++) yacc[mi][ni][c] = 0.0f;

    int nMt = nt + 1;
    #pragma unroll 1
    for (int mt = 0; mt < nMt; mt++) {
        int mb_ = mt << 6;
        int buf = mt & 1;
        CPWAIT0();              // K[mt], V[mt] resident
        __syncthreads();        // all warps past Y(mt-1)

        // issue K[mt+1] + V[mt+1] into other buffers (hidden under compute)
        if (mt + 1 < nMt) {
            int r = tid >> 2, c = (tid & 3) * 32;
            const __half* ksrc = Kg + (size_t)(mb_ + 64 + r)*DHEAD + c;
            #pragma unroll
            for (int i = 0; i < 4; i++)
                CP16(ksb[buf^1] + (uint32_t)(r*136 + c + i*8)*2u, ksrc + i*8);
            int vr = tid >> 1, vc = (tid & 1) * 32;
            const __half* vsrc = Vg + (size_t)vr*LSEQ + mb_ + 64 + vc;
            #pragma unroll
            for (int i = 0; i < 4; i++)
                CP16(vsb[buf^1] + (uint32_t)(vr*72 + vc + i*8)*2u, vsrc + i*8);
            CPCOMMIT();
        }

        const __half* K_ = Ks[buf];
        // S = Q K^T : warp tile 32 rows x 16 cols, k-depth 128 (8 k16 steps)
        float sacc[2][2][4];
        #pragma unroll
        for (int mi = 0; mi < 2; mi++)
            #pragma unroll
            for (int nj = 0; nj < 2; nj++)
                #pragma unroll
                for (int c = 0; c < 4; c++) sacc[mi][nj][c] = 0.0f;
        #pragma unroll
        for (int ks = 0; ks < 8; ks++) {
            int c = ks*16 + 2*tq;
            uint32_t af[2][4];
            #pragma unroll
            for (int mi = 0; mi < 2; mi++) {
                int r = wm*32 + mi*16 + q;
                af[mi][0] = LDU(Qs + r*136 + c);
                af[mi][1] = LDU(Qs + (r+8)*136 + c);
                af[mi][2] = LDU(Qs + r*136 + c + 8);
                af[mi][3] = LDU(Qs + (r+8)*136 + c + 8);
            }
            #pragma unroll
            for (int nj = 0; nj < 2; nj++) {
                int m = wn*16 + nj*8 + q;
                uint32_t b0 = LDU(K_ + m*136 + c);
                uint32_t b1 = LDU(K_ + m*136 + c + 8);
                mma16(sacc[0][nj], af[0][0], af[0][1], af[0][2], af[0][3], b0, b1);
                mma16(sacc[1][nj], af[1][0], af[1][1], af[1][2], af[1][3], b0, b1);
            }
        }

        // decay + store own 32x16 block of Ss (fp16)
        #pragma unroll
        for (int mi = 0; mi < 2; mi++) {
            #pragma unroll
            for (int hf = 0; hf < 2; hf++) {
                int r = wm*32 + mi*16 + q + hf*8;
                int n_ = nb + r;
                float pnv = pn[mi][hf];
                #pragma unroll
                for (int nj = 0; nj < 2; nj++) {
                    int m = wn*16 + nj*8 + 2*tq;
                    int mg = mb_ + m;
                    float2 ip = *(const float2*)(pm + mg);
                    float v0 = (n_ >= mg) ? sacc[mi][nj][hf*2+0] * (pnv*ip.x) : 0.0f;
                    float v1 = (n_ >  mg) ? sacc[mi][nj][hf*2+1] * (pnv*ip.y) : 0.0f;
                    *(__half2*)(Ss + r*72 + m) = __floats2half2_rn(v0, v1);
                }
            }
        }
        __syncthreads();   // S visible cross-warp; V[mt] already resident

        const __half* V_ = Vs[buf];
        // Y += S V^T : warp tile 32 rows x 32 cols, k-depth 64 (4 k16 steps)
        #pragma unroll
        for (int ks = 0; ks < 4; ks++) {
            int c = ks*16 + 2*tq;
            uint32_t af[2][4];
            #pragma unroll
            for (int mi = 0; mi < 2; mi++) {
                int r = wm*32 + mi*16 + q;
                af[mi][0] = LDU(Ss + r*72 + c);
                af[mi][1] = LDU(Ss + (r+8)*72 + c);
                af[mi][2] = LDU(Ss + r*72 + c + 8);
                af[mi][3] = LDU(Ss + (r+8)*72 + c + 8);
            }
            #pragma unroll
            for (int ni = 0; ni < 4; ni++) {
                int v = wn*32 + ni*8 + q;
                uint32_t b0 = LDU(V_ + v*72 + c);
                uint32_t b1 = LDU(V_ + v*72 + c + 8);
                mma16(yacc[0][ni], af[0][0], af[0][1], af[0][2], af[0][3], b0, b1);
                mma16(yacc[1][ni], af[1][0], af[1][1], af[1][2], af[1][3], b0, b1);
            }
        }
    }

    // write Y (f32): rows nb + wm*32 + mi*16 + q + hf*8, cols wn*32 + ni*8 + 2tq
    #pragma unroll
    for (int mi = 0; mi < 2; mi++) {
        #pragma unroll
        for (int hf = 0; hf < 2; hf++) {
            int row = wm*32 + mi*16 + q + hf*8;
            #pragma unroll
            for (int ni = 0; ni < 4; ni++) {
                int v = wn*32 + ni*8 + 2*tq;
                *(float2*)(Yg + (size_t)(nb + row)*DHEAD + v) =
                    make_float2(yacc[mi][ni][hf*2+0], yacc[mi][ni][hf*2+1]);
            }
        }
    }
}

// ---------------- group norm over head dim (128), transpose to [b,l,d] ------
__global__ __launch_bounds__(256) void groupnorm_kernel(
    const float* __restrict__ gw, const float* __restrict__ gb)
{
    int gtid = blockIdx.x*blockDim.x + threadIdx.x;
    int warp = gtid >> 5;
    int lane = gtid & 31;
    if (warp >= BATCH*NHEADS*LSEQ) return;
    const float* y = g_Y + (size_t)warp * DHEAD;
    float4 v = ((const float4*)y)[lane];
    float s  = v.x + v.y + v.z + v.w;
    float ss = v.x*v.x + v.y*v.y + v.z*v.z + v.w*v.w;
    #pragma unroll
    for (int o = 16; o > 0; o >>= 1) {
        s  += __shfl_xor_sync(0xffffffffu, s,  o);
        ss += __shfl_xor_sync(0xffffffffu, ss, o);
    }
    float mean = s * (1.0f/DHEAD);
    float var  = ss * (1.0f/DHEAD) - mean*mean;
    float rstd = rsqrtf(var + 1e-5f);
    int l  = warp & (LSEQ - 1);
    int h  = (warp >> 11) & (NHEADS - 1);
    int bb = warp >> 14;
    int dcol = h*DHEAD + (lane << 2);
    float4 w4 = *(const float4*)(gw + dcol);
    float4 b4 = *(const float4*)(gb + dcol);
    float4 o;
    o.x = (v.x - mean)*rstd*w4.x + b4.x;
    o.y = (v.y - mean)*rstd*w4.y + b4.y;
    o.z = (v.z - mean)*rstd*w4.z + b4.z;
    o.w = (v.w - mean)*rstd*w4.w + b4.w;
    *(float4*)(g_Yn + (size_t)(bb*LSEQ + l)*DMODEL + dcol) = o;
}

// ---------------- launch ----------------------------------------------------
extern "C" void kernel_launch(void* const* d_in, const int* in_sizes, int n_in,
                              void* d_out, int out_size) {
    const float* X  = (const float*)d_in[0];
    const float* WQ = (const float*)d_in[1];
    const float* WK = (const float*)d_in[2];
    const float* WV = (const float*)d_in[3];
    const float* WG = (const float*)d_in[4];
    const float* WO = (const float*)d_in[5];
    const float* gw = (const float*)d_in[6];
    const float* gb = (const float*)d_in[7];
    float* out = (float*)d_out;

    cudaFuncSetAttribute(mm_kernel, cudaFuncAttributeMaxDynamicSharedMemorySize, MM_SMEM);
    cudaFuncSetAttribute(attn_kernel, cudaFuncAttributeMaxDynamicSharedMemorySize, ATT_SMEM);

    init_tables_kernel<<<512, 256>>>();
    roundx_kernel<<<(MROWS*DMODEL/8)/256, 256>>>(X);
    wtrans_kernel<<<dim3(32, 160), dim3(32, 8)>>>(WQ, WK, WV, WG, WO);

    // QKV projection + rotary + V transpose
    mm_kernel<<<dim3(24, 64), 256, MM_SMEM>>>(nullptr, 0, 0);

    // retention attention (64-row tiles, 2 CTA/SM)
    attn_kernel<<<dim3(32, NHEADS, BATCH), 256, ATT_SMEM>>>();

    // group norm + transpose
    groupnorm_kernel<<<(BATCH*NHEADS*LSEQ*32)/256, 256>>>(gw, gb);

    // gate GEMM + silu*Yn
    mm_kernel<<<dim3(8, 64), 256, MM_SMEM>>>(nullptr, 1, 3072);

    // output GEMM
    mm_kernel<<<dim3(8, 64), 256, MM_SMEM>>>(out, 2, 4096);
}

// round 10
// speedup vs baseline: 1.3173x; 1.0214x over previous
#include <cuda_runtime.h>
#include <cuda_fp16.h>
#include <math.h>
#include <stdint.h>

#define BATCH 4
#define LSEQ 2048
#define DMODEL 1024
#define NHEADS 8
#define DHEAD 128
#define MROWS (BATCH*LSEQ)

// ---------------- device scratch --------------------------------------------
__device__ __half g_Wt[5120*1024];                // transposed weights [n][k] fp16
__device__ __half g_Xr[MROWS*DMODEL];             // fp16 X
__device__ __half g_Q [BATCH*NHEADS*LSEQ*DHEAD];  // [b,h,l,e]
__device__ __half g_K [BATCH*NHEADS*LSEQ*DHEAD];
__device__ __half g_Vt[BATCH*NHEADS*DHEAD*LSEQ];  // [b,h,v,l]
__device__ float  g_Y [BATCH*NHEADS*LSEQ*DHEAD];
__device__ float  g_Yn[MROWS*DMODEL];
__device__ __half g_Sx[MROWS*DMODEL];             // silu(G)*Yn fp16
__device__ float g_qc[LSEQ*64];
__device__ float g_qs[LSEQ*64];
__device__ float g_kc[LSEQ*64];
__device__ float g_ks[LSEQ*64];
__device__ float g_pn[NHEADS*LSEQ];               // gamma^l
__device__ float g_pm[NHEADS*LSEQ];               // gamma^-l

// ---------------- helpers ----------------------------------------------------
__device__ __forceinline__ uint32_t smem_u32(const void* p) {
    uint32_t a;
    asm("{ .reg .u64 t; cvta.to.shared.u64 t, %1; cvt.u32.u64 %0, t; }" : "=r"(a) : "l"(p));
    return a;
}
__device__ __forceinline__ void mma16(float d[4], uint32_t a0, uint32_t a1, uint32_t a2, uint32_t a3,
                                      uint32_t b0, uint32_t b1) {
    asm volatile(
        "mma.sync.aligned.m16n8k16.row.col.f32.f16.f16.f32 "
        "{%0,%1,%2,%3}, {%4,%5,%6,%7}, {%8,%9}, {%0,%1,%2,%3};"
        : "+f"(d[0]), "+f"(d[1]), "+f"(d[2]), "+f"(d[3])
        : "r"(a0), "r"(a1), "r"(a2), "r"(a3), "r"(b0), "r"(b1));
}
#define LDU(p) (*(const uint32_t*)(p))
#define CP16(dst, src)  asm volatile("cp.async.cg.shared.global [%0], [%1], 16;" :: "r"(dst), "l"(src) : "memory")
#define CPCOMMIT()      asm volatile("cp.async.commit_group;" ::: "memory")
#define CPWAIT0()       asm volatile("cp.async.wait_group 0;" ::: "memory")
#define CPWAIT1()       asm volatile("cp.async.wait_group 1;" ::: "memory")

// ---------------- table init -------------------------------------------------
__global__ void init_tables_kernel() {
    int idx = blockIdx.x*blockDim.x + threadIdx.x;
    if (idx < LSEQ*64) {
        int l = idx >> 6, j = idx & 63;
        float dh = (float)DHEAD;
        float base = (2.f*(float)j + 0.4f*dh) / (1.4f*dh);
        float scale = powf(base, (float)l / 512.0f);
        float inv_freq = powf(10000.0f, -(float)j / 64.0f);
        float arg = (float)l * inv_freq;
        float sv = sinf(arg), cv = cosf(arg);
        g_qc[idx] = cv * scale;
        g_qs[idx] = sv * scale;
        float iscale = 1.0f / scale;
        g_kc[idx] = cv * iscale;
        g_ks[idx] = sv * iscale;
    }
    if (idx < NHEADS*LSEQ) {
        int h = idx >> 11, k = idx & (LSEQ-1);
        float lg0 = logf(1.0f/32.0f), lg1 = logf(1.0f/512.0f);
        float lg = lg0 + (lg1 - lg0) * ((float)h / (float)(NHEADS-1));
        float gamma = 1.0f - expf(lg);
        double lng = (double)logf(gamma);
        g_pn[idx] = (float)exp((double)k * lng);
        g_pm[idx] = (float)exp(-(double)k * lng);
    }
}

// ---------------- X -> fp16 --------------------------------------------------
__global__ void roundx_kernel(const float* __restrict__ X) {
    int idx = blockIdx.x*blockDim.x + threadIdx.x;   // over /8
    float4 v0 = ((const float4*)X)[idx*2];
    float4 v1 = ((const float4*)X)[idx*2 + 1];
    __half2 h[4];
    h[0] = __floats2half2_rn(v0.x, v0.y);
    h[1] = __floats2half2_rn(v0.z, v0.w);
    h[2] = __floats2half2_rn(v1.x, v1.y);
    h[3] = __floats2half2_rn(v1.z, v1.w);
    *(uint4*)(g_Xr + (size_t)idx*8) = *(uint4*)h;
}

// ---------------- weight transpose -> fp16 ----------------------------------
__global__ void wtrans_kernel(const float* __restrict__ WQ, const float* __restrict__ WK,
                              const float* __restrict__ WV, const float* __restrict__ WG,
                              const float* __restrict__ WO) {
    __shared__ float t[32][33];
    int kT = blockIdx.x << 5, nT = blockIdx.y << 5;
    int tx = threadIdx.x, ty = threadIdx.y;   // 32 x 8
    #pragma unroll
    for (int r = 0; r < 4; r++) {
        int n = nT + tx, k = kT + ty + 8*r;
        float v;
        if (n < 3072) {
            int sel = n >> 10, h = (n >> 7) & 7, e = n & 127;
            const float* W = (sel == 0) ? WQ : (sel == 1) ? WK : WV;
            v = W[(size_t)h*131072 + (size_t)k*128 + e];
        } else if (n < 4096) {
            v = WG[(size_t)k*1024 + (n - 3072)];
        } else {
            v = WO[(size_t)k*1024 + (n - 4096)];
        }
        t[ty + 8*r][tx] = v;
    }
    __syncthreads();
    #pragma unroll
    for (int r = 0; r < 4; r++) {
        int n = nT + ty + 8*r, k = kT + tx;
        g_Wt[(size_t)n*1024 + k] = __float2half(t[tx][ty + 8*r]);
    }
}

// ---------------- unified fp16 mma GEMM: 3-stage, 1 barrier/chunk ------------
// 256 thr, 8 warps (4x2), warp tile 32x64. k-chunks of 64, triple buffered.
// smem: A[3][128][72] | B[3][128][72] halves = 108 KB -> 2 CTAs/SM
#define MM_SMEM (110592)
__global__ __launch_bounds__(256) void mm_kernel(float* __restrict__ Cout, int mode, int wRowOff) {
    extern __shared__ __half smh[];
    const int tid = threadIdx.x;
    const int wid = tid >> 5, lane = tid & 31;
    const int q = lane >> 2, tq = lane & 3;
    const int wm = wid & 3, wn = wid >> 2;
    const int rb = blockIdx.y << 7, cb = blockIdx.x << 7;

    const __half* Ap = ((mode == 2) ? g_Sx : g_Xr) + (size_t)rb * 1024;
    const __half* Bp = g_Wt + (size_t)(wRowOff + cb) * 1024;

    uint32_t smb = smem_u32(smh);
    // byte offsets: A bufs at 0/18432/36864, B bufs at 55296/73728/92160
    auto issue_chunk = [&](int kc, int s) {
        int kt = kc * 64;
        uint32_t ab = smb + (uint32_t)s * 18432u;
        uint32_t bb = smb + 55296u + (uint32_t)s * 18432u;
        #pragma unroll
        for (int i = 0; i < 4; i++) {
            int ch = tid + (i << 8);
            int r = ch >> 3, c8 = (ch & 7) << 3;
            CP16(ab + (uint32_t)(r*72 + c8)*2u, Ap + (size_t)r*1024 + kt + c8);
            CP16(bb + (uint32_t)(r*72 + c8)*2u, Bp + (size_t)r*1024 + kt + c8);
        }
        CPCOMMIT();
    };

    float acc[2][8][4];
    #pragma unroll
    for (int mi = 0; mi < 2; mi++)
        #pragma unroll
        for (int ni = 0; ni < 8; ni++)
            #pragma unroll
            for (int c = 0; c < 4; c++) acc[mi][ni][c] = 0.0f;

    issue_chunk(0, 0);
    issue_chunk(1, 1);

    #pragma unroll 1
    for (int k = 0; k < 16; k++) {
        int s = k % 3;
        if (k + 2 < 16) CPWAIT1(); else CPWAIT0();
        __syncthreads();                 // chunk k visible; all warps done chunk k-1
        if (k + 2 < 16) issue_chunk(k + 2, (k + 2) % 3);

        const __half* A_ = smh + s * 9216;
        const __half* B_ = smh + 27648 + s * 9216;
        #pragma unroll
        for (int ks = 0; ks < 4; ks++) {
            int c = ks*16 + 2*tq;
            uint32_t af[2][4];
            uint32_t bf[8][2];
            #pragma unroll
            for (int mi = 0; mi < 2; mi++) {
                int r = wm*32 + mi*16 + q;
                af[mi][0] = LDU(A_ + r*72 + c);
                af[mi][1] = LDU(A_ + (r+8)*72 + c);
                af[mi][2] = LDU(A_ + r*72 + c + 8);
                af[mi][3] = LDU(A_ + (r+8)*72 + c + 8);
            }
            #pragma unroll
            for (int ni = 0; ni < 8; ni++) {
                int n = wn*64 + ni*8 + q;
                bf[ni][0] = LDU(B_ + n*72 + c);
                bf[ni][1] = LDU(B_ + n*72 + c + 8);
            }
            #pragma unroll
            for (int ni = 0; ni < 8; ni++) {
                mma16(acc[0][ni], af[0][0], af[0][1], af[0][2], af[0][3], bf[ni][0], bf[ni][1]);
                mma16(acc[1][ni], af[1][0], af[1][1], af[1][2], af[1][3], bf[ni][0], bf[ni][1]);
            }
        }
    }

    // ---------------- epilogue ----------------
    int sel = 0, hh = 0;
    if (mode == 0) { sel = blockIdx.x >> 3; hh = blockIdx.x & 7; }

    #pragma unroll
    for (int mi = 0; mi < 2; mi++) {
        #pragma unroll
        for (int half_ = 0; half_ < 2; half_++) {
            int row = rb + wm*32 + mi*16 + q + half_*8;
            int bb = row >> 11, l = row & (LSEQ - 1);
            #pragma unroll
            for (int ni = 0; ni < 8; ni++) {
                int colb = wn*64 + ni*8 + 2*tq;
                float x1 = acc[mi][ni][half_*2 + 0];
                float x2 = acc[mi][ni][half_*2 + 1];
                if (mode == 0) {
                    size_t hbase = (size_t)(bb*NHEADS + hh);
                    if (sel == 2) {
                        __half* vt = g_Vt + hbase * (size_t)(DHEAD*LSEQ);
                        vt[(size_t)colb * LSEQ + l]       = __float2half(x1);
                        vt[(size_t)(colb + 1) * LSEQ + l] = __float2half(x2);
                    } else {
                        const float* ct = (sel == 0) ? g_qc : g_kc;
                        const float* st = (sel == 0) ? g_qs : g_ks;
                        int jj = colb >> 1;
                        float cv = ct[l*64 + jj], sv = st[l*64 + jj];
                        __half2 o = __floats2half2_rn(x1*cv - x2*sv, x2*cv + x1*sv);
                        __half* dst = ((sel == 0) ? g_Q : g_K) + (hbase*LSEQ + l)*DHEAD + colb;
                        *(__half2*)dst = o;
                    }
                } else if (mode == 1) {
                    size_t off = (size_t)row*1024 + cb + colb;
                    float2 yn = *(const float2*)(g_Yn + off);
                    __half2 o = __floats2half2_rn((x1 / (1.0f + expf(-x1))) * yn.x,
                                                  (x2 / (1.0f + expf(-x2))) * yn.y);
                    *(__half2*)(g_Sx + off) = o;
                } else {
                    size_t off = (size_t)row*1024 + cb + colb;
                    *(float2*)(Cout + off) = make_float2(x1, x2);
                }
            }
        }
    }
}

// ---------------- attention: fp16, pipelined (R7 known-good) -----------------
// smem halves: Qs[128][136] | Ks[2][64][136] | Vs[2][128][72] | Ss[128][72]
#define QS_O  0
#define KS0_O 17408
#define KS1_O 26112
#define VS0_O 34816
#define VS1_O 44032
#define SS_O  53248
#define ATT_SMEM (62464*2)
__global__ __launch_bounds__(256) void attn_kernel() {
    extern __shared__ __half smh[];
    __half* Qs = smh + QS_O;
    __half* Ks[2] = { smh + KS0_O, smh + KS1_O };
    __half* Vs[2] = { smh + VS0_O, smh + VS1_O };
    __half* Ss = smh + SS_O;
    uint32_t smb = smem_u32(smh);
    uint32_t qsb = smb + QS_O*2u;
    uint32_t ksb[2] = { smb + KS0_O*2u, smb + KS1_O*2u };
    uint32_t vsb[2] = { smb + VS0_O*2u, smb + VS1_O*2u };

    const int tid = threadIdx.x;
    const int wid = tid >> 5, lane = tid & 31;
    const int q = lane >> 2, tq = lane & 3;
    const int wm = wid & 3, wn = wid >> 2;

    int nt = (int)(gridDim.x - 1) - (int)blockIdx.x;   // big tiles first
    int h = blockIdx.y, b = blockIdx.z;
    int nb = nt << 7;

    size_t hb = (size_t)(b*NHEADS + h);
    const __half* Qg = g_Q + hb * (size_t)(LSEQ*DHEAD);
    const __half* Kg = g_K + hb * (size_t)(LSEQ*DHEAD);
    const __half* Vg = g_Vt + hb * (size_t)(DHEAD*LSEQ);
    float* Yg = g_Y + hb * (size_t)(LSEQ*DHEAD);
    const float* pm = g_pm + h*LSEQ;

    float pn[2][2];
    #pragma unroll
    for (int mi = 0; mi < 2; mi++)
        #pragma unroll
        for (int hf = 0; hf < 2; hf++)
            pn[mi][hf] = g_pn[h*LSEQ + nb + wm*32 + mi*16 + q + hf*8];

    // prologue: Q (32KB: 8 cp16/thr) + K[0] (16KB: 4/thr) + V[0] (16KB: 4/thr)
    {
        int r = tid >> 1, part = (tid & 1) * 64;
        const __half* src = Qg + (size_t)(nb + r)*DHEAD + part;
        #pragma unroll
        for (int i = 0; i < 8; i++)
            CP16(qsb + (uint32_t)(r*136 + part + i*8)*2u, src + i*8);
        int kr = tid >> 2, kc = (tid & 3) * 32;
        const __half* ksrc = Kg + (size_t)kr*DHEAD + kc;
        #pragma unroll
        for (int i = 0; i < 4; i++)
            CP16(ksb[0] + (uint32_t)(kr*136 + kc + i*8)*2u, ksrc + i*8);
        int vr = tid >> 1, vc = (tid & 1) * 32;
        const __half* vsrc = Vg + (size_t)vr*LSEQ + vc;
        #pragma unroll
        for (int i = 0; i < 4; i++)
            CP16(vsb[0] + (uint32_t)(vr*72 + vc + i*8)*2u, vsrc + i*8);
        CPCOMMIT();
    }

    float yacc[2][8][4];
    #pragma unroll
    for (int mi = 0; mi < 2; mi++)
        #pragma unroll
        for (int ni = 0; ni < 8; ni++)
            #pragma unroll
            for (int c = 0; c < 4; c++) yacc[mi][ni][c] = 0.0f;

    int nMt = 2*nt + 2;
    #pragma unroll 1
    for (int mt = 0; mt < nMt; mt++) {
        int mb_ = mt << 6;
        int buf = mt & 1;
        CPWAIT0();              // K[mt], V[mt] resident
        __syncthreads();        // all warps past Y(mt-1): other buffers free

        // issue K[mt+1] + V[mt+1] into the other buffers (hidden under compute)
        if (mt + 1 < nMt) {
            int kr = tid >> 2, kc = (tid & 3) * 32;
            const __half* ksrc = Kg + (size_t)(mb_ + 64 + kr)*DHEAD + kc;
            #pragma unroll
            for (int i = 0; i < 4; i++)
                CP16(ksb[buf^1] + (uint32_t)(kr*136 + kc + i*8)*2u, ksrc + i*8);
            int vr = tid >> 1, vc = (tid & 1) * 32;
            const __half* vsrc = Vg + (size_t)vr*LSEQ + mb_ + 64 + vc;
            #pragma unroll
            for (int i = 0; i < 4; i++)
                CP16(vsb[buf^1] + (uint32_t)(vr*72 + vc + i*8)*2u, vsrc + i*8);
            CPCOMMIT();
        }

        const __half* K_ = Ks[buf];
        // S = Q K^T : warp tile 32 rows x 32 cols, k-depth 128 (8 k16 steps)
        float sacc[2][4][4];
        #pragma unroll
        for (int mi = 0; mi < 2; mi++)
            #pragma unroll
            for (int ni = 0; ni < 4; ni++)
                #pragma unroll
                for (int c = 0; c < 4; c++) sacc[mi][ni][c] = 0.0f;
        #pragma unroll
        for (int ks = 0; ks < 8; ks++) {
            int c = ks*16 + 2*tq;
            uint32_t af[2][4];
            uint32_t bf[4][2];
            #pragma unroll
            for (int mi = 0; mi < 2; mi++) {
                int r = wm*32 + mi*16 + q;
                af[mi][0] = LDU(Qs + r*136 + c);
                af[mi][1] = LDU(Qs + (r+8)*136 + c);
                af[mi][2] = LDU(Qs + r*136 + c + 8);
                af[mi][3] = LDU(Qs + (r+8)*136 + c + 8);
            }
            #pragma unroll
            for (int ni = 0; ni < 4; ni++) {
                int m = wn*32 + ni*8 + q;
                bf[ni][0] = LDU(K_ + m*136 + c);
                bf[ni][1] = LDU(K_ + m*136 + c + 8);
            }
            #pragma unroll
            for (int ni = 0; ni < 4; ni++) {
                mma16(sacc[0][ni], af[0][0], af[0][1], af[0][2], af[0][3], bf[ni][0], bf[ni][1]);
                mma16(sacc[1][ni], af[1][0], af[1][1], af[1][2], af[1][3], bf[ni][0], bf[ni][1]);
            }
        }

        // decay + store own 32x32 block of Ss (fp16)
        #pragma unroll
        for (int mi = 0; mi < 2; mi++) {
            #pragma unroll
            for (int hf = 0; hf < 2; hf++) {
                int r = wm*32 + mi*16 + q + hf*8;
                int n_ = nb + r;
                float pnv = pn[mi][hf];
                #pragma unroll
                for (int ni = 0; ni < 4; ni++) {
                    int m = wn*32 + ni*8 + 2*tq;
                    int mg = mb_ + m;
                    float2 ip = *(const float2*)(pm + mg);
                    float v0 = (n_ >= mg) ? sacc[mi][ni][hf*2+0] * (pnv*ip.x) : 0.0f;
                    float v1 = (n_ >  mg) ? sacc[mi][ni][hf*2+1] * (pnv*ip.y) : 0.0f;
                    *(__half2*)(Ss + r*72 + m) = __floats2half2_rn(v0, v1);
                }
            }
        }
        __syncthreads();   // S visible cross-warp; V[mt] already resident

        const __half* V_ = Vs[buf];
        // Y += S V^T : warp tile 32 rows x 64 cols, k-depth 64 (4 k16 steps)
        #pragma unroll
        for (int ks = 0; ks < 4; ks++) {
            int c = ks*16 + 2*tq;
            uint32_t af[2][4];
            uint32_t bf[8][2];
            #pragma unroll
            for (int mi = 0; mi < 2; mi++) {
                int r = wm*32 + mi*16 + q;
                af[mi][0] = LDU(Ss + r*72 + c);
                af[mi][1] = LDU(Ss + (r+8)*72 + c);
                af[mi][2] = LDU(Ss + r*72 + c + 8);
                af[mi][3] = LDU(Ss + (r+8)*72 + c + 8);
            }
            #pragma unroll
            for (int ni = 0; ni < 8; ni++) {
                int v = wn*64 + ni*8 + q;
                bf[ni][0] = LDU(V_ + v*72 + c);
                bf[ni][1] = LDU(V_ + v*72 + c + 8);
            }
            #pragma unroll
            for (int ni = 0; ni < 8; ni++) {
                mma16(yacc[0][ni], af[0][0], af[0][1], af[0][2], af[0][3], bf[ni][0], bf[ni][1]);
                mma16(yacc[1][ni], af[1][0], af[1][1], af[1][2], af[1][3], bf[ni][0], bf[ni][1]);
            }
        }
    }

    // write Y (f32)
    #pragma unroll
    for (int mi = 0; mi < 2; mi++) {
        #pragma unroll
        for (int hf = 0; hf < 2; hf++) {
            int row = wm*32 + mi*16 + q + hf*8;
            #pragma unroll
            for (int ni = 0; ni < 8; ni++) {
                int v = wn*64 + ni*8 + 2*tq;
                *(float2*)(Yg + (size_t)(nb + row)*DHEAD + v) =
                    make_float2(yacc[mi][ni][hf*2+0], yacc[mi][ni][hf*2+1]);
            }
        }
    }
}

// ---------------- group norm over head dim (128), transpose to [b,l,d] ------
__global__ __launch_bounds__(256) void groupnorm_kernel(
    const float* __restrict__ gw, const float* __restrict__ gb)
{
    int gtid = blockIdx.x*blockDim.x + threadIdx.x;
    int warp = gtid >> 5;
    int lane = gtid & 31;
    if (warp >= BATCH*NHEADS*LSEQ) return;
    const float* y = g_Y + (size_t)warp * DHEAD;
    float4 v = ((const float4*)y)[lane];
    float s  = v.x + v.y + v.z + v.w;
    float ss = v.x*v.x + v.y*v.y + v.z*v.z + v.w*v.w;
    #pragma unroll
    for (int o = 16; o > 0; o >>= 1) {
        s  += __shfl_xor_sync(0xffffffffu, s,  o);
        ss += __shfl_xor_sync(0xffffffffu, ss, o);
    }
    float mean = s * (1.0f/DHEAD);
    float var  = ss * (1.0f/DHEAD) - mean*mean;
    float rstd = rsqrtf(var + 1e-5f);
    int l  = warp & (LSEQ - 1);
    int h  = (warp >> 11) & (NHEADS - 1);
    int bb = warp >> 14;
    int dcol = h*DHEAD + (lane << 2);
    float4 w4 = *(const float4*)(gw + dcol);
    float4 b4 = *(const float4*)(gb + dcol);
    float4 o;
    o.x = (v.x - mean)*rstd*w4.x + b4.x;
    o.y = (v.y - mean)*rstd*w4.y + b4.y;
    o.z = (v.z - mean)*rstd*w4.z + b4.z;
    o.w = (v.w - mean)*rstd*w4.w + b4.w;
    *(float4*)(g_Yn + (size_t)(bb*LSEQ + l)*DMODEL + dcol) = o;
}

// ---------------- launch ----------------------------------------------------
extern "C" void kernel_launch(void* const* d_in, const int* in_sizes, int n_in,
                              void* d_out, int out_size) {
    const float* X  = (const float*)d_in[0];
    const float* WQ = (const float*)d_in[1];
    const float* WK = (const float*)d_in[2];
    const float* WV = (const float*)d_in[3];
    const float* WG = (const float*)d_in[4];
    const float* WO = (const float*)d_in[5];
    const float* gw = (const float*)d_in[6];
    const float* gb = (const float*)d_in[7];
    float* out = (float*)d_out;

    cudaFuncSetAttribute(mm_kernel, cudaFuncAttributeMaxDynamicSharedMemorySize, MM_SMEM);
    cudaFuncSetAttribute(attn_kernel, cudaFuncAttributeMaxDynamicSharedMemorySize, ATT_SMEM);

    init_tables_kernel<<<512, 256>>>();
    roundx_kernel<<<(MROWS*DMODEL/8)/256, 256>>>(X);
    wtrans_kernel<<<dim3(32, 160), dim3(32, 8)>>>(WQ, WK, WV, WG, WO);

    // QKV projection + rotary + V transpose
    mm_kernel<<<dim3(24, 64), 256, MM_SMEM>>>(nullptr, 0, 0);

    // retention attention
    attn_kernel<<<dim3(16, NHEADS, BATCH), 256, ATT_SMEM>>>();

    // group norm + transpose
    groupnorm_kernel<<<(BATCH*NHEADS*LSEQ*32)/256, 256>>>(gw, gb);

    // gate GEMM + silu*Yn
    mm_kernel<<<dim3(8, 64), 256, MM_SMEM>>>(nullptr, 1, 3072);

    // output GEMM
    mm_kernel<<<dim3(8, 64), 256, MM_SMEM>>>(out, 2, 4096);
}

// round 11
// speedup vs baseline: 1.4355x; 1.0897x over previous
#include <cuda_runtime.h>
#include <cuda_fp16.h>
#include <math.h>
#include <stdint.h>

#define BATCH 4
#define LSEQ 2048
#define DMODEL 1024
#define NHEADS 8
#define DHEAD 128
#define MROWS (BATCH*LSEQ)

// ---------------- device scratch --------------------------------------------
__device__ __half g_Wt[5120*1024];                // transposed weights [n][k] fp16
__device__ __half g_Xr[MROWS*DMODEL];             // fp16 X
__device__ __half g_Q [BATCH*NHEADS*LSEQ*DHEAD];  // [b,h,l,e]
__device__ __half g_K [BATCH*NHEADS*LSEQ*DHEAD];
__device__ __half g_Vt[BATCH*NHEADS*DHEAD*LSEQ];  // [b,h,v,l]
__device__ float  g_Y [BATCH*NHEADS*LSEQ*DHEAD];
__device__ float  g_Yn[MROWS*DMODEL];
__device__ __half g_Sx[MROWS*DMODEL];             // silu(G)*Yn fp16
__device__ float g_qc[LSEQ*64];
__device__ float g_qs[LSEQ*64];
__device__ float g_kc[LSEQ*64];
__device__ float g_ks[LSEQ*64];
__device__ float g_pn[NHEADS*LSEQ];               // gamma^l
__device__ float g_pm[NHEADS*LSEQ];               // gamma^-l

// ---------------- helpers ----------------------------------------------------
__device__ __forceinline__ uint32_t smem_u32(const void* p) {
    uint32_t a;
    asm("{ .reg .u64 t; cvta.to.shared.u64 t, %1; cvt.u32.u64 %0, t; }" : "=r"(a) : "l"(p));
    return a;
}
__device__ __forceinline__ void mma16(float d[4], uint32_t a0, uint32_t a1, uint32_t a2, uint32_t a3,
                                      uint32_t b0, uint32_t b1) {
    asm volatile(
        "mma.sync.aligned.m16n8k16.row.col.f32.f16.f16.f32 "
        "{%0,%1,%2,%3}, {%4,%5,%6,%7}, {%8,%9}, {%0,%1,%2,%3};"
        : "+f"(d[0]), "+f"(d[1]), "+f"(d[2]), "+f"(d[3])
        : "r"(a0), "r"(a1), "r"(a2), "r"(a3), "r"(b0), "r"(b1));
}
#define LDU(p) (*(const uint32_t*)(p))
#define CP16(dst, src)  asm volatile("cp.async.cg.shared.global [%0], [%1], 16;" :: "r"(dst), "l"(src) : "memory")
#define CPCOMMIT()      asm volatile("cp.async.commit_group;" ::: "memory")
#define CPWAIT0()       asm volatile("cp.async.wait_group 0;" ::: "memory")
#define CPWAIT1()       asm volatile("cp.async.wait_group 1;" ::: "memory")

// ---------------- table init -------------------------------------------------
__global__ void init_tables_kernel() {
    int idx = blockIdx.x*blockDim.x + threadIdx.x;
    if (idx < LSEQ*64) {
        int l = idx >> 6, j = idx & 63;
        float dh = (float)DHEAD;
        float base = (2.f*(float)j + 0.4f*dh) / (1.4f*dh);
        float scale = powf(base, (float)l / 512.0f);
        float inv_freq = powf(10000.0f, -(float)j / 64.0f);
        float arg = (float)l * inv_freq;
        float sv = sinf(arg), cv = cosf(arg);
        g_qc[idx] = cv * scale;
        g_qs[idx] = sv * scale;
        float iscale = 1.0f / scale;
        g_kc[idx] = cv * iscale;
        g_ks[idx] = sv * iscale;
    }
    if (idx < NHEADS*LSEQ) {
        int h = idx >> 11, k = idx & (LSEQ-1);
        float lg0 = logf(1.0f/32.0f), lg1 = logf(1.0f/512.0f);
        float lg = lg0 + (lg1 - lg0) * ((float)h / (float)(NHEADS-1));
        float gamma = 1.0f - expf(lg);
        double lng = (double)logf(gamma);
        g_pn[idx] = (float)exp((double)k * lng);
        g_pm[idx] = (float)exp(-(double)k * lng);
    }
}

// ---------------- X -> fp16 --------------------------------------------------
__global__ void roundx_kernel(const float* __restrict__ X) {
    int idx = blockIdx.x*blockDim.x + threadIdx.x;   // over /8
    float4 v0 = ((const float4*)X)[idx*2];
    float4 v1 = ((const float4*)X)[idx*2 + 1];
    __half2 h[4];
    h[0] = __floats2half2_rn(v0.x, v0.y);
    h[1] = __floats2half2_rn(v0.z, v0.w);
    h[2] = __floats2half2_rn(v1.x, v1.y);
    h[3] = __floats2half2_rn(v1.z, v1.w);
    *(uint4*)(g_Xr + (size_t)idx*8) = *(uint4*)h;
}

// ---------------- weight transpose -> fp16 ----------------------------------
__global__ void wtrans_kernel(const float* __restrict__ WQ, const float* __restrict__ WK,
                              const float* __restrict__ WV, const float* __restrict__ WG,
                              const float* __restrict__ WO) {
    __shared__ float t[32][33];
    int kT = blockIdx.x << 5, nT = blockIdx.y << 5;
    int tx = threadIdx.x, ty = threadIdx.y;   // 32 x 8
    #pragma unroll
    for (int r = 0; r < 4; r++) {
        int n = nT + tx, k = kT + ty + 8*r;
        float v;
        if (n < 3072) {
            int sel = n >> 10, h = (n >> 7) & 7, e = n & 127;
            const float* W = (sel == 0) ? WQ : (sel == 1) ? WK : WV;
            v = W[(size_t)h*131072 + (size_t)k*128 + e];
        } else if (n < 4096) {
            v = WG[(size_t)k*1024 + (n - 3072)];
        } else {
            v = WO[(size_t)k*1024 + (n - 4096)];
        }
        t[ty + 8*r][tx] = v;
    }
    __syncthreads();
    #pragma unroll
    for (int r = 0; r < 4; r++) {
        int n = nT + ty + 8*r, k = kT + tx;
        g_Wt[(size_t)n*1024 + k] = __float2half(t[tx][ty + 8*r]);
    }
}

// ---------------- unified fp16 mma GEMM: 3-stage, 1 barrier/chunk ------------
// 256 thr, 8 warps (4x2), warp tile 32x64. k-chunks of 64, triple buffered.
// smem: A[3][128][72] | B[3][128][72] halves = 108 KB -> 2 CTAs/SM
#define MM_SMEM (110592)
__global__ __launch_bounds__(256) void mm_kernel(float* __restrict__ Cout, int mode, int wRowOff) {
    extern __shared__ __half smh[];
    const int tid = threadIdx.x;
    const int wid = tid >> 5, lane = tid & 31;
    const int q = lane >> 2, tq = lane & 3;
    const int wm = wid & 3, wn = wid >> 2;
    const int rb = blockIdx.y << 7, cb = blockIdx.x << 7;

    const __half* Ap = ((mode == 2) ? g_Sx : g_Xr) + (size_t)rb * 1024;
    const __half* Bp = g_Wt + (size_t)(wRowOff + cb) * 1024;

    uint32_t smb = smem_u32(smh);
    auto issue_chunk = [&](int kc, int s) {
        int kt = kc * 64;
        uint32_t ab = smb + (uint32_t)s * 18432u;
        uint32_t bb = smb + 55296u + (uint32_t)s * 18432u;
        #pragma unroll
        for (int i = 0; i < 4; i++) {
            int ch = tid + (i << 8);
            int r = ch >> 3, c8 = (ch & 7) << 3;
            CP16(ab + (uint32_t)(r*72 + c8)*2u, Ap + (size_t)r*1024 + kt + c8);
            CP16(bb + (uint32_t)(r*72 + c8)*2u, Bp + (size_t)r*1024 + kt + c8);
        }
        CPCOMMIT();
    };

    float acc[2][8][4];
    #pragma unroll
    for (int mi = 0; mi < 2; mi++)
        #pragma unroll
        for (int ni = 0; ni < 8; ni++)
            #pragma unroll
            for (int c = 0; c < 4; c++) acc[mi][ni][c] = 0.0f;

    issue_chunk(0, 0);
    issue_chunk(1, 1);

    #pragma unroll 1
    for (int k = 0; k < 16; k++) {
        int s = k % 3;
        if (k + 2 < 16) CPWAIT1(); else CPWAIT0();
        __syncthreads();                 // chunk k visible; all warps done chunk k-1
        if (k + 2 < 16) issue_chunk(k + 2, (k + 2) % 3);

        const __half* A_ = smh + s * 9216;
        const __half* B_ = smh + 27648 + s * 9216;
        #pragma unroll
        for (int ks = 0; ks < 4; ks++) {
            int c = ks*16 + 2*tq;
            uint32_t af[2][4];
            uint32_t bf[8][2];
            #pragma unroll
            for (int mi = 0; mi < 2; mi++) {
                int r = wm*32 + mi*16 + q;
                af[mi][0] = LDU(A_ + r*72 + c);
                af[mi][1] = LDU(A_ + (r+8)*72 + c);
                af[mi][2] = LDU(A_ + r*72 + c + 8);
                af[mi][3] = LDU(A_ + (r+8)*72 + c + 8);
            }
            #pragma unroll
            for (int ni = 0; ni < 8; ni++) {
                int n = wn*64 + ni*8 + q;
                bf[ni][0] = LDU(B_ + n*72 + c);
                bf[ni][1] = LDU(B_ + n*72 + c + 8);
            }
            #pragma unroll
            for (int ni = 0; ni < 8; ni++) {
                mma16(acc[0][ni], af[0][0], af[0][1], af[0][2], af[0][3], bf[ni][0], bf[ni][1]);
                mma16(acc[1][ni], af[1][0], af[1][1], af[1][2], af[1][3], bf[ni][0], bf[ni][1]);
            }
        }
    }

    // ---------------- epilogue ----------------
    int sel = 0, hh = 0;
    if (mode == 0) { sel = blockIdx.x >> 3; hh = blockIdx.x & 7; }

    #pragma unroll
    for (int mi = 0; mi < 2; mi++) {
        #pragma unroll
        for (int half_ = 0; half_ < 2; half_++) {
            int row = rb + wm*32 + mi*16 + q + half_*8;
            int bb = row >> 11, l = row & (LSEQ - 1);
            #pragma unroll
            for (int ni = 0; ni < 8; ni++) {
                int colb = wn*64 + ni*8 + 2*tq;
                float x1 = acc[mi][ni][half_*2 + 0];
                float x2 = acc[mi][ni][half_*2 + 1];
                if (mode == 0) {
                    size_t hbase = (size_t)(bb*NHEADS + hh);
                    if (sel == 2) {
                        __half* vt = g_Vt + hbase * (size_t)(DHEAD*LSEQ);
                        vt[(size_t)colb * LSEQ + l]       = __float2half(x1);
                        vt[(size_t)(colb + 1) * LSEQ + l] = __float2half(x2);
                    } else {
                        const float* ct = (sel == 0) ? g_qc : g_kc;
                        const float* st = (sel == 0) ? g_qs : g_ks;
                        int jj = colb >> 1;
                        float cv = ct[l*64 + jj], sv = st[l*64 + jj];
                        __half2 o = __floats2half2_rn(x1*cv - x2*sv, x2*cv + x1*sv);
                        __half* dst = ((sel == 0) ? g_Q : g_K) + (hbase*LSEQ + l)*DHEAD + colb;
                        *(__half2*)dst = o;
                    }
                } else if (mode == 1) {
                    size_t off = (size_t)row*1024 + cb + colb;
                    float2 yn = *(const float2*)(g_Yn + off);
                    __half2 o = __floats2half2_rn((x1 / (1.0f + expf(-x1))) * yn.x,
                                                  (x2 / (1.0f + expf(-x2))) * yn.y);
                    *(__half2*)(g_Sx + off) = o;
                } else {
                    size_t off = (size_t)row*1024 + cb + colb;
                    *(float2*)(Cout + off) = make_float2(x1, x2);
                }
            }
        }
    }
}

// ---------------- attention: fp16, single-V, 104 KB -> 2 CTA/SM --------------
// smem halves: Qs[128][136] | Ks[2][64][136] | Vs[128][72] | Ss[128][72]
#define QS_O  0
#define KS0_O 17408
#define KS1_O 26112
#define VS_O  34816
#define SS_O  44032
#define ATT_SMEM (53248*2)
__global__ __launch_bounds__(256, 2) void attn_kernel() {
    extern __shared__ __half smh[];
    __half* Qs = smh + QS_O;
    __half* Ks[2] = { smh + KS0_O, smh + KS1_O };
    __half* Vs = smh + VS_O;
    __half* Ss = smh + SS_O;
    uint32_t smb = smem_u32(smh);
    uint32_t qsb = smb + QS_O*2u;
    uint32_t ksb[2] = { smb + KS0_O*2u, smb + KS1_O*2u };
    uint32_t vsb = smb + VS_O*2u;

    const int tid = threadIdx.x;
    const int wid = tid >> 5, lane = tid & 31;
    const int q = lane >> 2, tq = lane & 3;
    const int wm = wid & 3, wn = wid >> 2;

    int nt = (int)(gridDim.x - 1) - (int)blockIdx.x;   // big tiles first
    int h = blockIdx.y, b = blockIdx.z;
    int nb = nt << 7;

    size_t hb = (size_t)(b*NHEADS + h);
    const __half* Qg = g_Q + hb * (size_t)(LSEQ*DHEAD);
    const __half* Kg = g_K + hb * (size_t)(LSEQ*DHEAD);
    const __half* Vg = g_Vt + hb * (size_t)(DHEAD*LSEQ);
    float* Yg = g_Y + hb * (size_t)(LSEQ*DHEAD);
    const float* pm = g_pm + h*LSEQ;

    float pn[2][2];
    #pragma unroll
    for (int mi = 0; mi < 2; mi++)
        #pragma unroll
        for (int hf = 0; hf < 2; hf++)
            pn[mi][hf] = g_pn[h*LSEQ + nb + wm*32 + mi*16 + q + hf*8];

    // prologue: Q (32KB: 8 cp16/thr) + K[0] (16KB: 4/thr), one commit group
    {
        int r = tid >> 1, part = (tid & 1) * 64;
        const __half* src = Qg + (size_t)(nb + r)*DHEAD + part;
        #pragma unroll
        for (int i = 0; i < 8; i++)
            CP16(qsb + (uint32_t)(r*136 + part + i*8)*2u, src + i*8);
        int kr = tid >> 2, kc = (tid & 3) * 32;
        const __half* ksrc = Kg + (size_t)kr*DHEAD + kc;
        #pragma unroll
        for (int i = 0; i < 4; i++)
            CP16(ksb[0] + (uint32_t)(kr*136 + kc + i*8)*2u, ksrc + i*8);
        CPCOMMIT();
    }

    float yacc[2][8][4];
    #pragma unroll
    for (int mi = 0; mi < 2; mi++)
        #pragma unroll
        for (int ni = 0; ni < 8; ni++)
            #pragma unroll
            for (int c = 0; c < 4; c++) yacc[mi][ni][c] = 0.0f;

    int nMt = 2*nt + 2;
    #pragma unroll 1
    for (int mt = 0; mt < nMt; mt++) {
        int mb_ = mt << 6;
        int buf = mt & 1;
        CPWAIT0();              // K[mt] resident (only pending group)
        __syncthreads();        // K visible; all warps past Y(mt-1): V/S buffers free

        // issue V[mt] (single buffer; hidden under S-phase)
        {
            int vr = tid >> 1, vc = (tid & 1) * 32;
            const __half* vsrc = Vg + (size_t)vr*LSEQ + mb_ + vc;
            #pragma unroll
            for (int i = 0; i < 4; i++)
                CP16(vsb + (uint32_t)(vr*72 + vc + i*8)*2u, vsrc + i*8);
            CPCOMMIT();
        }
        // issue K[mt+1] (hidden until next iter top)
        if (mt + 1 < nMt) {
            int kr = tid >> 2, kc = (tid & 3) * 32;
            const __half* ksrc = Kg + (size_t)(mb_ + 64 + kr)*DHEAD + kc;
            #pragma unroll
            for (int i = 0; i < 4; i++)
                CP16(ksb[buf^1] + (uint32_t)(kr*136 + kc + i*8)*2u, ksrc + i*8);
            CPCOMMIT();
        }

        const __half* K_ = Ks[buf];
        // S = Q K^T : warp tile 32 rows x 32 cols, k-depth 128 (8 k16 steps)
        float sacc[2][4][4];
        #pragma unroll
        for (int mi = 0; mi < 2; mi++)
            #pragma unroll
            for (int ni = 0; ni < 4; ni++)
                #pragma unroll
                for (int c = 0; c < 4; c++) sacc[mi][ni][c] = 0.0f;
        #pragma unroll
        for (int ks = 0; ks < 8; ks++) {
            int c = ks*16 + 2*tq;
            uint32_t af[2][4];
            uint32_t bf[4][2];
            #pragma unroll
            for (int mi = 0; mi < 2; mi++) {
                int r = wm*32 + mi*16 + q;
                af[mi][0] = LDU(Qs + r*136 + c);
                af[mi][1] = LDU(Qs + (r+8)*136 + c);
                af[mi][2] = LDU(Qs + r*136 + c + 8);
                af[mi][3] = LDU(Qs + (r+8)*136 + c + 8);
            }
            #pragma unroll
            for (int ni = 0; ni < 4; ni++) {
                int m = wn*32 + ni*8 + q;
                bf[ni][0] = LDU(K_ + m*136 + c);
                bf[ni][1] = LDU(K_ + m*136 + c + 8);
            }
            #pragma unroll
            for (int ni = 0; ni < 4; ni++) {
                mma16(sacc[0][ni], af[0][0], af[0][1], af[0][2], af[0][3], bf[ni][0], bf[ni][1]);
                mma16(sacc[1][ni], af[1][0], af[1][1], af[1][2], af[1][3], bf[ni][0], bf[ni][1]);
            }
        }

        // decay + store own 32x32 block of Ss (fp16)
        #pragma unroll
        for (int mi = 0; mi < 2; mi++) {
            #pragma unroll
            for (int hf = 0; hf < 2; hf++) {
                int r = wm*32 + mi*16 + q + hf*8;
                int n_ = nb + r;
                float pnv = pn[mi][hf];
                #pragma unroll
                for (int ni = 0; ni < 4; ni++) {
                    int m = wn*32 + ni*8 + 2*tq;
                    int mg = mb_ + m;
                    float2 ip = *(const float2*)(pm + mg);
                    float v0 = (n_ >= mg) ? sacc[mi][ni][hf*2+0] * (pnv*ip.x) : 0.0f;
                    float v1 = (n_ >  mg) ? sacc[mi][ni][hf*2+1] * (pnv*ip.y) : 0.0f;
                    *(__half2*)(Ss + r*72 + m) = __floats2half2_rn(v0, v1);
                }
            }
        }
        if (mt + 1 < nMt) CPWAIT1(); else CPWAIT0();   // V[mt] resident
        __syncthreads();                                // Ss + Vs visible

        // Y += S V^T : warp tile 32 rows x 64 cols, k-depth 64 (4 k16 steps)
        #pragma unroll
        for (int ks = 0; ks < 4; ks++) {
            int c = ks*16 + 2*tq;
            uint32_t af[2][4];
            uint32_t bf[8][2];
            #pragma unroll
            for (int mi = 0; mi < 2; mi++) {
                int r = wm*32 + mi*16 + q;
                af[mi][0] = LDU(Ss + r*72 + c);
                af[mi][1] = LDU(Ss + (r+8)*72 + c);
                af[mi][2] = LDU(Ss + r*72 + c + 8);
                af[mi][3] = LDU(Ss + (r+8)*72 + c + 8);
            }
            #pragma unroll
            for (int ni = 0; ni < 8; ni++) {
                int v = wn*64 + ni*8 + q;
                bf[ni][0] = LDU(Vs + v*72 + c);
                bf[ni][1] = LDU(Vs + v*72 + c + 8);
            }
            #pragma unroll
            for (int ni = 0; ni < 8; ni++) {
                mma16(yacc[0][ni], af[0][0], af[0][1], af[0][2], af[0][3], bf[ni][0], bf[ni][1]);
                mma16(yacc[1][ni], af[1][0], af[1][1], af[1][2], af[1][3], bf[ni][0], bf[ni][1]);
            }
        }
    }

    // write Y (f32)
    #pragma unroll
    for (int mi = 0; mi < 2; mi++) {
        #pragma unroll
        for (int hf = 0; hf < 2; hf++) {
            int row = wm*32 + mi*16 + q + hf*8;
            #pragma unroll
            for (int ni = 0; ni < 8; ni++) {
                int v = wn*64 + ni*8 + 2*tq;
                *(float2*)(Yg + (size_t)(nb + row)*DHEAD + v) =
                    make_float2(yacc[mi][ni][hf*2+0], yacc[mi][ni][hf*2+1]);
            }
        }
    }
}

// ---------------- group norm over head dim (128), transpose to [b,l,d] ------
__global__ __launch_bounds__(256) void groupnorm_kernel(
    const float* __restrict__ gw, const float* __restrict__ gb)
{
    int gtid = blockIdx.x*blockDim.x + threadIdx.x;
    int warp = gtid >> 5;
    int lane = gtid & 31;
    if (warp >= BATCH*NHEADS*LSEQ) return;
    const float* y = g_Y + (size_t)warp * DHEAD;
    float4 v = ((const float4*)y)[lane];
    float s  = v.x + v.y + v.z + v.w;
    float ss = v.x*v.x + v.y*v.y + v.z*v.z + v.w*v.w;
    #pragma unroll
    for (int o = 16; o > 0; o >>= 1) {
        s  += __shfl_xor_sync(0xffffffffu, s,  o);
        ss += __shfl_xor_sync(0xffffffffu, ss, o);
    }
    float mean = s * (1.0f/DHEAD);
    float var  = ss * (1.0f/DHEAD) - mean*mean;
    float rstd = rsqrtf(var + 1e-5f);
    int l  = warp & (LSEQ - 1);
    int h  = (warp >> 11) & (NHEADS - 1);
    int bb = warp >> 14;
    int dcol = h*DHEAD + (lane << 2);
    float4 w4 = *(const float4*)(gw + dcol);
    float4 b4 = *(const float4*)(gb + dcol);
    float4 o;
    o.x = (v.x - mean)*rstd*w4.x + b4.x;
    o.y = (v.y - mean)*rstd*w4.y + b4.y;
    o.z = (v.z - mean)*rstd*w4.z + b4.z;
    o.w = (v.w - mean)*rstd*w4.w + b4.w;
    *(float4*)(g_Yn + (size_t)(bb*LSEQ + l)*DMODEL + dcol) = o;
}

// ---------------- launch ----------------------------------------------------
extern "C" void kernel_launch(void* const* d_in, const int* in_sizes, int n_in,
                              void* d_out, int out_size) {
    const float* X  = (const float*)d_in[0];
    const float* WQ = (const float*)d_in[1];
    const float* WK = (const float*)d_in[2];
    const float* WV = (const float*)d_in[3];
    const float* WG = (const float*)d_in[4];
    const float* WO = (const float*)d_in[5];
    const float* gw = (const float*)d_in[6];
    const float* gb = (const float*)d_in[7];
    float* out = (float*)d_out;

    cudaFuncSetAttribute(mm_kernel, cudaFuncAttributeMaxDynamicSharedMemorySize, MM_SMEM);
    cudaFuncSetAttribute(attn_kernel, cudaFuncAttributeMaxDynamicSharedMemorySize, ATT_SMEM);

    init_tables_kernel<<<512, 256>>>();
    roundx_kernel<<<(MROWS*DMODEL/8)/256, 256>>>(X);
    wtrans_kernel<<<dim3(32, 160), dim3(32, 8)>>>(WQ, WK, WV, WG, WO);

    // QKV projection + rotary + V transpose
    mm_kernel<<<dim3(24, 64), 256, MM_SMEM>>>(nullptr, 0, 0);

    // retention attention (2 CTA/SM)
    attn_kernel<<<dim3(16, NHEADS, BATCH), 256, ATT_SMEM>>>();

    // group norm + transpose
    groupnorm_kernel<<<(BATCH*NHEADS*LSEQ*32)/256, 256>>>(gw, gb);

    // gate GEMM + silu*Yn
    mm_kernel<<<dim3(8, 64), 256, MM_SMEM>>>(nullptr, 1, 3072);

    // output GEMM
    mm_kernel<<<dim3(8, 64), 256, MM_SMEM>>>(out, 2, 4096);
}

// round 12
// speedup vs baseline: 1.5160x; 1.0561x over previous
#include <cuda_runtime.h>
#include <cuda_fp16.h>
#include <math.h>
#include <stdint.h>

#define BATCH 4
#define LSEQ 2048
#define DMODEL 1024
#define NHEADS 8
#define DHEAD 128
#define MROWS (BATCH*LSEQ)

// ---------------- device scratch --------------------------------------------
__device__ __half g_Wt[5120*1024];                // transposed weights [n][k] fp16
__device__ __half g_Xr[MROWS*DMODEL];             // fp16 X
__device__ __half g_Q [BATCH*NHEADS*LSEQ*DHEAD];  // [b,h,l,e]
__device__ __half g_K [BATCH*NHEADS*LSEQ*DHEAD];
__device__ __half g_Vt[BATCH*NHEADS*DHEAD*LSEQ];  // [b,h,v,l]
__device__ float  g_Yn[MROWS*DMODEL];
__device__ __half g_Sx[MROWS*DMODEL];             // silu(G)*Yn fp16
__device__ float g_qc[LSEQ*64];
__device__ float g_qs[LSEQ*64];
__device__ float g_kc[LSEQ*64];
__device__ float g_ks[LSEQ*64];
__device__ float g_pn[NHEADS*LSEQ];               // gamma^l
__device__ float g_pm[NHEADS*LSEQ];               // gamma^-l
__device__ int   g_win[NHEADS];                   // decay window (elements)

// ---------------- helpers ----------------------------------------------------
__device__ __forceinline__ uint32_t smem_u32(const void* p) {
    uint32_t a;
    asm("{ .reg .u64 t; cvta.to.shared.u64 t, %1; cvt.u32.u64 %0, t; }" : "=r"(a) : "l"(p));
    return a;
}
__device__ __forceinline__ void mma16(float d[4], uint32_t a0, uint32_t a1, uint32_t a2, uint32_t a3,
                                      uint32_t b0, uint32_t b1) {
    asm volatile(
        "mma.sync.aligned.m16n8k16.row.col.f32.f16.f16.f32 "
        "{%0,%1,%2,%3}, {%4,%5,%6,%7}, {%8,%9}, {%0,%1,%2,%3};"
        : "+f"(d[0]), "+f"(d[1]), "+f"(d[2]), "+f"(d[3])
        : "r"(a0), "r"(a1), "r"(a2), "r"(a3), "r"(b0), "r"(b1));
}
#define LDU(p) (*(const uint32_t*)(p))
#define CP16(dst, src)  asm volatile("cp.async.cg.shared.global [%0], [%1], 16;" :: "r"(dst), "l"(src) : "memory")
#define CPCOMMIT()      asm volatile("cp.async.commit_group;" ::: "memory")
#define CPWAIT0()       asm volatile("cp.async.wait_group 0;" ::: "memory")
#define CPWAIT1()       asm volatile("cp.async.wait_group 1;" ::: "memory")

// ---------------- table init -------------------------------------------------
__global__ void init_tables_kernel() {
    int idx = blockIdx.x*blockDim.x + threadIdx.x;
    if (idx < LSEQ*64) {
        int l = idx >> 6, j = idx & 63;
        float dh = (float)DHEAD;
        float base = (2.f*(float)j + 0.4f*dh) / (1.4f*dh);
        float scale = powf(base, (float)l / 512.0f);
        float inv_freq = powf(10000.0f, -(float)j / 64.0f);
        float arg = (float)l * inv_freq;
        float sv = sinf(arg), cv = cosf(arg);
        g_qc[idx] = cv * scale;
        g_qs[idx] = sv * scale;
        float iscale = 1.0f / scale;
        g_kc[idx] = cv * iscale;
        g_ks[idx] = sv * iscale;
    }
    if (idx < NHEADS*LSEQ) {
        int h = idx >> 11, k = idx & (LSEQ-1);
        float lg0 = logf(1.0f/32.0f), lg1 = logf(1.0f/512.0f);
        float lg = lg0 + (lg1 - lg0) * ((float)h / (float)(NHEADS-1));
        float gamma = 1.0f - expf(lg);
        double lng = (double)logf(gamma);
        g_pn[idx] = (float)exp((double)k * lng);
        g_pm[idx] = (float)exp(-(double)k * lng);
        if (k == 0) {
            // decay window: gamma^W = 1e-5  ->  W = ln(1e-5)/ln(gamma)
            double W = 11.512925 / (-lng);
            g_win[h] = (W >= 2047.0) ? 2047 : (int)W;
        }
    }
}

// ---------------- X -> fp16 --------------------------------------------------
__global__ void roundx_kernel(const float* __restrict__ X) {
    int idx = blockIdx.x*blockDim.x + threadIdx.x;   // over /8
    float4 v0 = ((const float4*)X)[idx*2];
    float4 v1 = ((const float4*)X)[idx*2 + 1];
    __half2 h[4];
    h[0] = __floats2half2_rn(v0.x, v0.y);
    h[1] = __floats2half2_rn(v0.z, v0.w);
    h[2] = __floats2half2_rn(v1.x, v1.y);
    h[3] = __floats2half2_rn(v1.z, v1.w);
    *(uint4*)(g_Xr + (size_t)idx*8) = *(uint4*)h;
}

// ---------------- weight transpose -> fp16 ----------------------------------
__global__ void wtrans_kernel(const float* __restrict__ WQ, const float* __restrict__ WK,
                              const float* __restrict__ WV, const float* __restrict__ WG,
                              const float* __restrict__ WO) {
    __shared__ float t[32][33];
    int kT = blockIdx.x << 5, nT = blockIdx.y << 5;
    int tx = threadIdx.x, ty = threadIdx.y;   // 32 x 8
    #pragma unroll
    for (int r = 0; r < 4; r++) {
        int n = nT + tx, k = kT + ty + 8*r;
        float v;
        if (n < 3072) {
            int sel = n >> 10, h = (n >> 7) & 7, e = n & 127;
            const float* W = (sel == 0) ? WQ : (sel == 1) ? WK : WV;
            v = W[(size_t)h*131072 + (size_t)k*128 + e];
        } else if (n < 4096) {
            v = WG[(size_t)k*1024 + (n - 3072)];
        } else {
            v = WO[(size_t)k*1024 + (n - 4096)];
        }
        t[ty + 8*r][tx] = v;
    }
    __syncthreads();
    #pragma unroll
    for (int r = 0; r < 4; r++) {
        int n = nT + ty + 8*r, k = kT + tx;
        g_Wt[(size_t)n*1024 + k] = __float2half(t[tx][ty + 8*r]);
    }
}

// ---------------- unified fp16 mma GEMM: 3-stage, 1 barrier/chunk ------------
#define MM_SMEM (110592)
__global__ __launch_bounds__(256) void mm_kernel(float* __restrict__ Cout, int mode, int wRowOff) {
    extern __shared__ __half smh[];
    const int tid = threadIdx.x;
    const int wid = tid >> 5, lane = tid & 31;
    const int q = lane >> 2, tq = lane & 3;
    const int wm = wid & 3, wn = wid >> 2;
    const int rb = blockIdx.y << 7, cb = blockIdx.x << 7;

    const __half* Ap = ((mode == 2) ? g_Sx : g_Xr) + (size_t)rb * 1024;
    const __half* Bp = g_Wt + (size_t)(wRowOff + cb) * 1024;

    uint32_t smb = smem_u32(smh);
    auto issue_chunk = [&](int kc, int s) {
        int kt = kc * 64;
        uint32_t ab = smb + (uint32_t)s * 18432u;
        uint32_t bb = smb + 55296u + (uint32_t)s * 18432u;
        #pragma unroll
        for (int i = 0; i < 4; i++) {
            int ch = tid + (i << 8);
            int r = ch >> 3, c8 = (ch & 7) << 3;
            CP16(ab + (uint32_t)(r*72 + c8)*2u, Ap + (size_t)r*1024 + kt + c8);
            CP16(bb + (uint32_t)(r*72 + c8)*2u, Bp + (size_t)r*1024 + kt + c8);
        }
        CPCOMMIT();
    };

    float acc[2][8][4];
    #pragma unroll
    for (int mi = 0; mi < 2; mi++)
        #pragma unroll
        for (int ni = 0; ni < 8; ni++)
            #pragma unroll
            for (int c = 0; c < 4; c++) acc[mi][ni][c] = 0.0f;

    issue_chunk(0, 0);
    issue_chunk(1, 1);

    #pragma unroll 1
    for (int k = 0; k < 16; k++) {
        int s = k % 3;
        if (k + 2 < 16) CPWAIT1(); else CPWAIT0();
        __syncthreads();
        if (k + 2 < 16) issue_chunk(k + 2, (k + 2) % 3);

        const __half* A_ = smh + s * 9216;
        const __half* B_ = smh + 27648 + s * 9216;
        #pragma unroll
        for (int ks = 0; ks < 4; ks++) {
            int c = ks*16 + 2*tq;
            uint32_t af[2][4];
            uint32_t bf[8][2];
            #pragma unroll
            for (int mi = 0; mi < 2; mi++) {
                int r = wm*32 + mi*16 + q;
                af[mi][0] = LDU(A_ + r*72 + c);
                af[mi][1] = LDU(A_ + (r+8)*72 + c);
                af[mi][2] = LDU(A_ + r*72 + c + 8);
                af[mi][3] = LDU(A_ + (r+8)*72 + c + 8);
            }
            #pragma unroll
            for (int ni = 0; ni < 8; ni++) {
                int n = wn*64 + ni*8 + q;
                bf[ni][0] = LDU(B_ + n*72 + c);
                bf[ni][1] = LDU(B_ + n*72 + c + 8);
            }
            #pragma unroll
            for (int ni = 0; ni < 8; ni++) {
                mma16(acc[0][ni], af[0][0], af[0][1], af[0][2], af[0][3], bf[ni][0], bf[ni][1]);
                mma16(acc[1][ni], af[1][0], af[1][1], af[1][2], af[1][3], bf[ni][0], bf[ni][1]);
            }
        }
    }

    // ---------------- epilogue ----------------
    int sel = 0, hh = 0;
    if (mode == 0) { sel = blockIdx.x >> 3; hh = blockIdx.x & 7; }

    #pragma unroll
    for (int mi = 0; mi < 2; mi++) {
        #pragma unroll
        for (int half_ = 0; half_ < 2; half_++) {
            int row = rb + wm*32 + mi*16 + q + half_*8;
            int bb = row >> 11, l = row & (LSEQ - 1);
            #pragma unroll
            for (int ni = 0; ni < 8; ni++) {
                int colb = wn*64 + ni*8 + 2*tq;
                float x1 = acc[mi][ni][half_*2 + 0];
                float x2 = acc[mi][ni][half_*2 + 1];
                if (mode == 0) {
                    size_t hbase = (size_t)(bb*NHEADS + hh);
                    if (sel == 2) {
                        __half* vt = g_Vt + hbase * (size_t)(DHEAD*LSEQ);
                        vt[(size_t)colb * LSEQ + l]       = __float2half(x1);
                        vt[(size_t)(colb + 1) * LSEQ + l] = __float2half(x2);
                    } else {
                        const float* ct = (sel == 0) ? g_qc : g_kc;
                        const float* st = (sel == 0) ? g_qs : g_ks;
                        int jj = colb >> 1;
                        float cv = ct[l*64 + jj], sv = st[l*64 + jj];
                        __half2 o = __floats2half2_rn(x1*cv - x2*sv, x2*cv + x1*sv);
                        __half* dst = ((sel == 0) ? g_Q : g_K) + (hbase*LSEQ + l)*DHEAD + colb;
                        *(__half2*)dst = o;
                    }
                } else if (mode == 1) {
                    size_t off = (size_t)row*1024 + cb + colb;
                    float2 yn = *(const float2*)(g_Yn + off);
                    __half2 o = __floats2half2_rn((x1 / (1.0f + expf(-x1))) * yn.x,
                                                  (x2 / (1.0f + expf(-x2))) * yn.y);
                    *(__half2*)(g_Sx + off) = o;
                } else {
                    size_t off = (size_t)row*1024 + cb + colb;
                    *(float2*)(Cout + off) = make_float2(x1, x2);
                }
            }
        }
    }
}

// ---------------- attention + fused groupnorm --------------------------------
// 104 KB smem -> 2 CTA/SM. Decay-window truncation per head.
// smem halves: Qs[128][136] | Ks[2][64][136] | Vs[128][72] | Ss[128][72]
#define QS_O  0
#define KS0_O 17408
#define KS1_O 26112
#define VS_O  34816
#define SS_O  44032
#define ATT_SMEM (53248*2)
__global__ __launch_bounds__(256, 2) void attn_kernel(
    const float* __restrict__ gw, const float* __restrict__ gb)
{
    extern __shared__ __half smh[];
    __half* Qs = smh + QS_O;
    __half* Ks[2] = { smh + KS0_O, smh + KS1_O };
    __half* Vs = smh + VS_O;
    __half* Ss = smh + SS_O;
    uint32_t smb = smem_u32(smh);
    uint32_t qsb = smb + QS_O*2u;
    uint32_t ksb[2] = { smb + KS0_O*2u, smb + KS1_O*2u };
    uint32_t vsb = smb + VS_O*2u;

    const int tid = threadIdx.x;
    const int wid = tid >> 5, lane = tid & 31;
    const int q = lane >> 2, tq = lane & 3;
    const int wm = wid & 3, wn = wid >> 2;

    int nt = (int)(gridDim.x - 1) - (int)blockIdx.x;   // big tiles first
    int h = blockIdx.y, b = blockIdx.z;
    int nb = nt << 7;

    size_t hb = (size_t)(b*NHEADS + h);
    const __half* Qg = g_Q + hb * (size_t)(LSEQ*DHEAD);
    const __half* Kg = g_K + hb * (size_t)(LSEQ*DHEAD);
    const __half* Vg = g_Vt + hb * (size_t)(DHEAD*LSEQ);
    const float* pm = g_pm + h*LSEQ;

    int nMt = 2*nt + 2;
    int mt0 = (nb - g_win[h]) >> 6;          // first m-step within decay window
    if (mt0 < 0) mt0 = 0;

    float pn[2][2];
    #pragma unroll
    for (int mi = 0; mi < 2; mi++)
        #pragma unroll
        for (int hf = 0; hf < 2; hf++)
            pn[mi][hf] = g_pn[h*LSEQ + nb + wm*32 + mi*16 + q + hf*8];

    // prologue: Q (8 cp16/thr) + K[mt0] (4/thr), one commit group
    {
        int r = tid >> 1, part = (tid & 1) * 64;
        const __half* src = Qg + (size_t)(nb + r)*DHEAD + part;
        #pragma unroll
        for (int i = 0; i < 8; i++)
            CP16(qsb + (uint32_t)(r*136 + part + i*8)*2u, src + i*8);
        int kr = tid >> 2, kc = (tid & 3) * 32;
        const __half* ksrc = Kg + (size_t)(mt0*64 + kr)*DHEAD + kc;
        #pragma unroll
        for (int i = 0; i < 4; i++)
            CP16(ksb[0] + (uint32_t)(kr*136 + kc + i*8)*2u, ksrc + i*8);
        CPCOMMIT();
    }

    float yacc[2][8][4];
    #pragma unroll
    for (int mi = 0; mi < 2; mi++)
        #pragma unroll
        for (int ni = 0; ni < 8; ni++)
            #pragma unroll
            for (int c = 0; c < 4; c++) yacc[mi][ni][c] = 0.0f;

    #pragma unroll 1
    for (int mt = mt0; mt < nMt; mt++) {
        int mb_ = mt << 6;
        int buf = (mt - mt0) & 1;
        CPWAIT0();              // K[mt] resident (only pending group)
        __syncthreads();        // K visible; all warps past Y(mt-1)

        // issue V[mt] (single buffer; hidden under S-phase)
        {
            int vr = tid >> 1, vc = (tid & 1) * 32;
            const __half* vsrc = Vg + (size_t)vr*LSEQ + mb_ + vc;
            #pragma unroll
            for (int i = 0; i < 4; i++)
                CP16(vsb + (uint32_t)(vr*72 + vc + i*8)*2u, vsrc + i*8);
            CPCOMMIT();
        }
        // issue K[mt+1]
        if (mt + 1 < nMt) {
            int kr = tid >> 2, kc = (tid & 3) * 32;
            const __half* ksrc = Kg + (size_t)(mb_ + 64 + kr)*DHEAD + kc;
            #pragma unroll
            for (int i = 0; i < 4; i++)
                CP16(ksb[buf^1] + (uint32_t)(kr*136 + kc + i*8)*2u, ksrc + i*8);
            CPCOMMIT();
        }

        const __half* K_ = Ks[buf];
        // S = Q K^T : warp tile 32x32, k-depth 128 (8 k16 steps)
        float sacc[2][4][4];
        #pragma unroll
        for (int mi = 0; mi < 2; mi++)
            #pragma unroll
            for (int ni = 0; ni < 4; ni++)
                #pragma unroll
                for (int c = 0; c < 4; c++) sacc[mi][ni][c] = 0.0f;
        #pragma unroll
        for (int ks = 0; ks < 8; ks++) {
            int c = ks*16 + 2*tq;
            uint32_t af[2][4];
            uint32_t bf[4][2];
            #pragma unroll
            for (int mi = 0; mi < 2; mi++) {
                int r = wm*32 + mi*16 + q;
                af[mi][0] = LDU(Qs + r*136 + c);
                af[mi][1] = LDU(Qs + (r+8)*136 + c);
                af[mi][2] = LDU(Qs + r*136 + c + 8);
                af[mi][3] = LDU(Qs + (r+8)*136 + c + 8);
            }
            #pragma unroll
            for (int ni = 0; ni < 4; ni++) {
                int m = wn*32 + ni*8 + q;
                bf[ni][0] = LDU(K_ + m*136 + c);
                bf[ni][1] = LDU(K_ + m*136 + c + 8);
            }
            #pragma unroll
            for (int ni = 0; ni < 4; ni++) {
                mma16(sacc[0][ni], af[0][0], af[0][1], af[0][2], af[0][3], bf[ni][0], bf[ni][1]);
                mma16(sacc[1][ni], af[1][0], af[1][1], af[1][2], af[1][3], bf[ni][0], bf[ni][1]);
            }
        }

        // decay + store own 32x32 block of Ss (fp16)
        #pragma unroll
        for (int mi = 0; mi < 2; mi++) {
            #pragma unroll
            for (int hf = 0; hf < 2; hf++) {
                int r = wm*32 + mi*16 + q + hf*8;
                int n_ = nb + r;
                float pnv = pn[mi][hf];
                #pragma unroll
                for (int ni = 0; ni < 4; ni++) {
                    int m = wn*32 + ni*8 + 2*tq;
                    int mg = mb_ + m;
                    float2 ip = *(const float2*)(pm + mg);
                    float v0 = (n_ >= mg) ? sacc[mi][ni][hf*2+0] * (pnv*ip.x) : 0.0f;
                    float v1 = (n_ >  mg) ? sacc[mi][ni][hf*2+1] * (pnv*ip.y) : 0.0f;
                    *(__half2*)(Ss + r*72 + m) = __floats2half2_rn(v0, v1);
                }
            }
        }
        if (mt + 1 < nMt) CPWAIT1(); else CPWAIT0();   // V[mt] resident
        __syncthreads();                                // Ss + Vs visible

        // Y += S V^T : warp tile 32x64, k-depth 64 (4 k16 steps)
        #pragma unroll
        for (int ks = 0; ks < 4; ks++) {
            int c = ks*16 + 2*tq;
            uint32_t af[2][4];
            uint32_t bf[8][2];
            #pragma unroll
            for (int mi = 0; mi < 2; mi++) {
                int r = wm*32 + mi*16 + q;
                af[mi][0] = LDU(Ss + r*72 + c);
                af[mi][1] = LDU(Ss + (r+8)*72 + c);
                af[mi][2] = LDU(Ss + r*72 + c + 8);
                af[mi][3] = LDU(Ss + (r+8)*72 + c + 8);
            }
            #pragma unroll
            for (int ni = 0; ni < 8; ni++) {
                int v = wn*64 + ni*8 + q;
                bf[ni][0] = LDU(Vs + v*72 + c);
                bf[ni][1] = LDU(Vs + v*72 + c + 8);
            }
            #pragma unroll
            for (int ni = 0; ni < 8; ni++) {
                mma16(yacc[0][ni], af[0][0], af[0][1], af[0][2], af[0][3], bf[ni][0], bf[ni][1]);
                mma16(yacc[1][ni], af[1][0], af[1][1], af[1][2], af[1][3], bf[ni][0], bf[ni][1]);
            }
        }
    }

    // -------- fused group norm over head dim + transposed write to g_Yn ------
    __syncthreads();                       // all warps done reading Vs/Ss
    float* fb = (float*)smh;               // 128 rows x 4 floats (s0,ss0,s1,ss1)
    #pragma unroll
    for (int mi = 0; mi < 2; mi++) {
        #pragma unroll
        for (int hf = 0; hf < 2; hf++) {
            int row = wm*32 + mi*16 + hf*8 + q;
            float s = 0.0f, ss = 0.0f;
            #pragma unroll
            for (int ni = 0; ni < 8; ni++) {
                float a = yacc[mi][ni][hf*2+0], b2 = yacc[mi][ni][hf*2+1];
                s += a + b2; ss += a*a + b2*b2;
            }
            s  += __shfl_xor_sync(0xffffffffu, s, 1);
            ss += __shfl_xor_sync(0xffffffffu, ss, 1);
            s  += __shfl_xor_sync(0xffffffffu, s, 2);
            ss += __shfl_xor_sync(0xffffffffu, ss, 2);
            if (tq == 0) { fb[row*4 + wn*2] = s; fb[row*4 + wn*2 + 1] = ss; }
        }
    }
    __syncthreads();
    #pragma unroll
    for (int mi = 0; mi < 2; mi++) {
        #pragma unroll
        for (int hf = 0; hf < 2; hf++) {
            int row = wm*32 + mi*16 + hf*8 + q;
            float s  = fb[row*4 + 0] + fb[row*4 + 2];
            float ss = fb[row*4 + 1] + fb[row*4 + 3];
            float mean = s * (1.0f/DHEAD);
            float var  = ss * (1.0f/DHEAD) - mean*mean;
            float rstd = rsqrtf(var + 1e-5f);
            int l = nb + row;
            float* dst = g_Yn + ((size_t)(b*LSEQ + l))*DMODEL + h*DHEAD;
            #pragma unroll
            for (int ni = 0; ni < 8; ni++) {
                int col = wn*64 + ni*8 + 2*tq;
                float2 w2 = *(const float2*)(gw + h*DHEAD + col);
                float2 b2 = *(const float2*)(gb + h*DHEAD + col);
                float y0 = yacc[mi][ni][hf*2+0], y1 = yacc[mi][ni][hf*2+1];
                float2 o;
                o.x = (y0 - mean)*rstd*w2.x + b2.x;
                o.y = (y1 - mean)*rstd*w2.y + b2.y;
                *(float2*)(dst + col) = o;
            }
        }
    }
}

// ---------------- launch ----------------------------------------------------
extern "C" void kernel_launch(void* const* d_in, const int* in_sizes, int n_in,
                              void* d_out, int out_size) {
    const float* X  = (const float*)d_in[0];
    const float* WQ = (const float*)d_in[1];
    const float* WK = (const float*)d_in[2];
    const float* WV = (const float*)d_in[3];
    const float* WG = (const float*)d_in[4];
    const float* WO = (const float*)d_in[5];
    const float* gw = (const float*)d_in[6];
    const float* gb = (const float*)d_in[7];
    float* out = (float*)d_out;

    cudaFuncSetAttribute(mm_kernel, cudaFuncAttributeMaxDynamicSharedMemorySize, MM_SMEM);
    cudaFuncSetAttribute(attn_kernel, cudaFuncAttributeMaxDynamicSharedMemorySize, ATT_SMEM);

    init_tables_kernel<<<512, 256>>>();
    roundx_kernel<<<(MROWS*DMODEL/8)/256, 256>>>(X);
    wtrans_kernel<<<dim3(32, 160), dim3(32, 8)>>>(WQ, WK, WV, WG, WO);

    // QKV projection + rotary + V transpose
    mm_kernel<<<dim3(24, 64), 256, MM_SMEM>>>(nullptr, 0, 0);

    // retention attention + fused group norm (2 CTA/SM, decay-windowed)
    attn_kernel<<<dim3(16, NHEADS, BATCH), 256, ATT_SMEM>>>(gw, gb);

    // gate GEMM + silu*Yn
    mm_kernel<<<dim3(8, 64), 256, MM_SMEM>>>(nullptr, 1, 3072);

    // output GEMM
    mm_kernel<<<dim3(8, 64), 256, MM_SMEM>>>(out, 2, 4096);
}